// round 11
// baseline (speedup 1.0000x reference)
#include <cuda_runtime.h>
#include <cuda_fp16.h>
#include <cstdint>
#include <cstddef>

#define NPOI 4096
#define DD   64
#define NB   8
#define DAYS 4
#define LL   64
#define NDROWS 32
#define NPOS   256
#define NINT 101
#define KC   8
#define MT   128
#define KT   64
#define NC   (NPOI/KT)
#define NC2  (NPOI/KC/KT)
#define BUF_BYTES 24576
#define LUT_OFF   (2*BUF_BYTES)
#define LUT_BYTES (NINT*32*4)
#define SMEM_G    (LUT_OFF + LUT_BYTES)        /* 62080: single LUT table */
#define SMEM_G2   (SMEM_G + 512)

typedef unsigned long long u64;
typedef unsigned int u32;

__device__ __align__(16) unsigned char g_bk[(size_t)NPOI * NPOI];
__device__ unsigned char g_diag[NPOI];
__device__ int   g_histT[NINT * NPOI];
__device__ float g_lut[NB * NINT];
__device__ float g_cntf[NB * NINT];
__device__ float g_invdeg[NB * NPOI];
__device__ int   g_rows[NB * NPOS];
__device__ float g_Y0[(size_t)NB * NPOI * DD];
__device__ float g_L1[(size_t)NB * NPOI * DD];
__device__ float g_Y1[(size_t)NB * NPOI * DD];
__device__ __align__(16) __half g_Yt[(size_t)NB * DD * NPOI];
__device__ __align__(16) __half g_Y1t[(size_t)NB * DD * NPOI];
__device__ float g_part[(size_t)KC * NB * NPOS * DD];

__device__ __forceinline__ u32 smem_u32(const void* p) {
    u32 a; asm("{ .reg .u64 t; cvta.to.shared.u64 t, %1; cvt.u32.u64 %0, t; }" : "=r"(a) : "l"(p));
    return a;
}
__device__ __forceinline__ u32 swz(u32 o) { return o ^ ((o >> 3) & 0x70); }
__device__ __forceinline__ void ldsm4(u32& r0, u32& r1, u32& r2, u32& r3, u32 a) {
    asm volatile("ldmatrix.sync.aligned.m8n8.x4.shared.b16 {%0,%1,%2,%3}, [%4];"
        : "=r"(r0), "=r"(r1), "=r"(r2), "=r"(r3) : "r"(a));
}
__device__ __forceinline__ void mma16816(float* c, const u32* a, u32 b0, u32 b1) {
    asm volatile("mma.sync.aligned.m16n8k16.row.col.f32.f16.f16.f32 "
        "{%0,%1,%2,%3}, {%4,%5,%6,%7}, {%8,%9}, {%0,%1,%2,%3};"
        : "+f"(c[0]), "+f"(c[1]), "+f"(c[2]), "+f"(c[3])
        : "r"(a[0]), "r"(a[1]), "r"(a[2]), "r"(a[3]), "r"(b0), "r"(b1));
}
#define CPA16(dst, src) asm volatile("cp.async.cg.shared.global [%0], [%1], 16;" :: "r"(dst), "l"(src))
#define CPCOMMIT()      asm volatile("cp.async.commit_group;")
#define CPWAIT0()       asm volatile("cp.async.wait_group 0;")

// single-table LUT convert (verified in R9): 32 bucket bytes -> 32 fp16
__device__ __forceinline__ void conv_store_A1(const u32* ml, const uint4* pa,
                                              char* Ab, const u32* aaddr) {
    #pragma unroll
    for (int u2 = 0; u2 < 2; u2++) {
        union { uint4 v; unsigned char b[16]; } q; q.v = pa[u2];
        #pragma unroll
        for (int hq = 0; hq < 2; hq++) {
            uint4 o;
            o.x = ml[q.b[hq*8+0]*32] | (ml[q.b[hq*8+1]*32] << 16);
            o.y = ml[q.b[hq*8+2]*32] | (ml[q.b[hq*8+3]*32] << 16);
            o.z = ml[q.b[hq*8+4]*32] | (ml[q.b[hq*8+5]*32] << 16);
            o.w = ml[q.b[hq*8+6]*32] | (ml[q.b[hq*8+7]*32] << 16);
            *(uint4*)(Ab + aaddr[u2*2+hq]) = o;
        }
    }
}

__device__ __forceinline__ void mma_chunk(u32 Ab_u, u32 Bb_u, u32 arow, u32 brow,
                                          float (&acc)[2][4][4]) {
    #pragma unroll
    for (int kk = 0; kk < 4; kk++) {
        const u32 kby = (u32)(kk * 32);
        u32 afr[2][4];
        #pragma unroll
        for (int mi = 0; mi < 2; mi++)
            ldsm4(afr[mi][0], afr[mi][1], afr[mi][2], afr[mi][3],
                  Ab_u + swz(arow + mi * 16 * 128 + kby));
        #pragma unroll
        for (int ni2 = 0; ni2 < 2; ni2++) {
            u32 r0, r1, r2, r3;
            ldsm4(r0, r1, r2, r3, Bb_u + swz(brow + ni2 * 16 * 128 + kby));
            #pragma unroll
            for (int mi = 0; mi < 2; mi++) {
                mma16816(acc[mi][ni2 * 2],     afr[mi], r0, r2);
                mma16816(acc[mi][ni2 * 2 + 1], afr[mi], r1, r3);
            }
        }
    }
}

// fused: blocks 0..4095 = bucket+hist; block 4096 = per-sample setup
__global__ __launch_bounds__(256) void buckhist_setup_kernel(const float* __restrict__ dist,
                                                             const int* __restrict__ seq,
                                                             const int* __restrict__ ids) {
    __shared__ int sh[NINT];
    __shared__ int sord[NDROWS];
    __shared__ int scnt[NB][NINT];
    int t = threadIdx.x;
    if (blockIdx.x < NPOI) {
        int i = blockIdx.x;
        if (t < NINT) sh[t] = 0;
        __syncthreads();
        const float* row = dist + (size_t)i * NPOI;
        union { uint4 v; unsigned char b[16]; } o;
        #pragma unroll
        for (int v = 0; v < 4; v++) {
            float4 f = *(const float4*)(row + t * 16 + v * 4);
            o.b[v*4+0] = (unsigned char)min(100, (int)floorf(f.x * 2.0f) + 1);
            o.b[v*4+1] = (unsigned char)min(100, (int)floorf(f.y * 2.0f) + 1);
            o.b[v*4+2] = (unsigned char)min(100, (int)floorf(f.z * 2.0f) + 1);
            o.b[v*4+3] = (unsigned char)min(100, (int)floorf(f.w * 2.0f) + 1);
        }
        #pragma unroll
        for (int m = 0; m < 16; m++) atomicAdd(&sh[o.b[m]], 1);
        *(uint4*)(g_bk + (size_t)i * NPOI + t * 16) = o.v;
        if ((i >> 4) == t) g_diag[i] = o.b[i & 15];
        __syncthreads();
        if (t < NINT) g_histT[t * NPOI + i] = sh[t];
        return;
    }
    if (t < NDROWS) {
        int my = ids[t], pos = 0;
        for (int q = 0; q < NDROWS; q++) {
            int v = ids[q];
            if (v < my || (v == my && q < t)) pos++;
        }
        sord[pos] = t;
    }
    for (int e = t; e < NB * NINT; e += 256) (&scnt[0][0])[e] = 0;
    __syncthreads();
    for (int e = t; e < NB * NPOS; e += 256) {
        int s = e >> 8, pos = e & 255, day = pos >> 6, l = pos & 63;
        g_rows[e] = seq[sord[s * DAYS + day] * LL + l] - 1;
    }
    for (int e = t; e < NB * (LL - 1); e += 256) {
        int s = e / (LL - 1), tt = e % (LL - 1);
        int lrow = sord[s * DAYS + (DAYS - 1)];
        int a = seq[lrow * LL + tt] - 1;
        int b = seq[lrow * LL + tt + 1] - 1;
        float dv = dist[(size_t)a * NPOI + b];
        int idx = (int)ceilf(dv * 2.0f);
        idx = idx < 0 ? 0 : (idx > 100 ? 100 : idx);
        atomicAdd(&scnt[s][idx], 1);
    }
    __syncthreads();
    for (int e = t; e < NB * NINT; e += 256) {
        int cv = (&scnt[0][0])[e];
        g_lut[e]  = (float)cv / 63.0f;
        g_cntf[e] = (float)cv;
    }
}

__global__ __launch_bounds__(256) void deg_kernel() {
    __shared__ float lc[NB][NINT];
    int t = threadIdx.x;
    for (int e = t; e < NB * NINT; e += 256) (&lc[0][0])[e] = g_lut[e];
    __syncthreads();
    int i = blockIdx.x * 256 + t;
    int dg = g_diag[i];
    float sums[NB];
    #pragma unroll
    for (int s = 0; s < NB; s++) sums[s] = 1.0f - lc[s][dg];
    #pragma unroll 101
    for (int k = 0; k < NINT; k++) {
        float h = (float)g_histT[k * NPOI + i];
        #pragma unroll
        for (int s = 0; s < NB; s++) sums[s] += lc[s][k] * h;
    }
    #pragma unroll
    for (int s = 0; s < NB; s++)
        g_invdeg[s * NPOI + i] = 1.0f / sqrtf(fmaxf(sums[s], 1e-24f));
}

__global__ __launch_bounds__(256) void y0t_kernel(const float* __restrict__ poi) {
    __shared__ float ts[64][65];
    int s = blockIdx.y, jbase = blockIdx.x * 64, t = threadIdx.x;
    #pragma unroll
    for (int r = 0; r < 16; r++) {
        int idx = r * 256 + t;
        int jl = idx >> 6, d = idx & 63;
        int j = jbase + jl;
        float y = poi[(size_t)(j + 1) * DD + d] * g_invdeg[s * NPOI + j];
        g_Y0[((size_t)s * NPOI + j) * DD + d] = y;
        ts[jl][d] = y;
    }
    __syncthreads();
    #pragma unroll
    for (int r = 0; r < 16; r++) {
        int idx = r * 256 + t;
        int d = idx >> 6, jl = idx & 63;
        g_Yt[((size_t)s * DD + d) * NPOI + jbase + jl] = __float2half(ts[jl][d]);
    }
}

__global__ __launch_bounds__(256) void y1t_kernel() {
    __shared__ float ts[64][65];
    int s = blockIdx.y, jbase = blockIdx.x * 64, t = threadIdx.x;
    #pragma unroll
    for (int r = 0; r < 16; r++) {
        int idx = r * 256 + t;
        int jl = idx >> 6, d = idx & 63;
        ts[jl][d] = g_Y1[((size_t)s * NPOI + jbase + jl) * DD + d];
    }
    __syncthreads();
    #pragma unroll
    for (int r = 0; r < 16; r++) {
        int idx = r * 256 + t;
        int d = idx >> 6, jl = idx & 63;
        g_Y1t[((size_t)s * DD + d) * NPOI + jbase + jl] = __float2half(ts[jl][d]);
    }
}

extern __shared__ __align__(1024) char dsm[];

// layer-1: MT=128, 256 thr, single LUT, occ 3
__global__ __launch_bounds__(256, 3) void gemm1_mma_kernel() {
    const int t = threadIdx.x, wid = t >> 5, lane = t & 31;
    const int s = blockIdx.y;
    const int rowbase = blockIdx.x * MT;
    u32* lut = (u32*)(dsm + LUT_OFF);
    const u32 base_u = smem_u32(dsm);

    for (int e = t; e < NINT * 32; e += 256) {
        __half h = __float2half(g_cntf[s * NINT + (e >> 5)]);
        lut[e] = (u32)*(unsigned short*)&h;
    }
    __syncthreads();
    const u32* ml = lut + lane;

    const int pm = t >> 1, ph = t & 1;
    const int bd = t >> 2, bq = t & 3;
    const unsigned char* gA = g_bk + (size_t)(rowbase + pm) * NPOI + ph * 32;
    const __half* gBrow = g_Yt + ((size_t)s * DD + bd) * NPOI;
    u32 aaddr[4];
    #pragma unroll
    for (int u2 = 0; u2 < 2; u2++)
        #pragma unroll
        for (int hq = 0; hq < 2; hq++)
            aaddr[u2*2+hq] = swz((u32)(pm * 128 + ph * 64 + u2 * 32 + hq * 16));
    const u32 boff0 = swz((u32)(bd * 128 + bq * 16));
    const u32 boff1 = swz((u32)(bd * 128 + (bq + 4) * 16));

    const int wm = wid & 3, wn = wid >> 2;
    float acc[2][4][4];
    #pragma unroll
    for (int a = 0; a < 2; a++)
        #pragma unroll
        for (int b = 0; b < 4; b++)
            #pragma unroll
            for (int c = 0; c < 4; c++) acc[a][b][c] = 0.0f;

    const u32 arow = (u32)((wm * 32 + (lane & 15)) * 128 + (lane >> 4) * 16);
    const u32 brow = (u32)((wn * 32 + (lane & 15)) * 128 + (lane >> 4) * 16);

    uint4 pa[2];
    pa[0] = *(const uint4*)(gA);  pa[1] = *(const uint4*)(gA + 16);
    CPA16(base_u + 16384 + boff0, gBrow + bq * 8);
    CPA16(base_u + 16384 + boff1, gBrow + (bq + 4) * 8);
    CPCOMMIT();
    conv_store_A1(ml, pa, dsm, aaddr);
    CPWAIT0();
    __syncthreads();

    for (int c = 0; c < NC; c++) {
        const u32 bufo = (u32)(c & 1) * BUF_BYTES;
        const u32 nbufo = (u32)((c + 1) & 1) * BUF_BYTES;
        if (c + 1 < NC) {
            int kb = (c + 1) * KT;
            pa[0] = *(const uint4*)(gA + kb);  pa[1] = *(const uint4*)(gA + kb + 16);
            CPA16(base_u + nbufo + 16384 + boff0, gBrow + kb + bq * 8);
            CPA16(base_u + nbufo + 16384 + boff1, gBrow + kb + (bq + 4) * 8);
            CPCOMMIT();
        }
        mma_chunk(base_u + bufo, base_u + bufo + 16384, arow, brow, acc);
        if (c + 1 < NC) conv_store_A1(ml, pa, dsm + nbufo, aaddr);
        CPWAIT0();
        __syncthreads();
    }

    #pragma unroll
    for (int mi = 0; mi < 2; mi++) {
        #pragma unroll
        for (int e2 = 0; e2 < 2; e2++) {
            int i = rowbase + wm * 32 + mi * 16 + (lane >> 2) + e2 * 8;
            float idg = g_invdeg[s * NPOI + i];
            float dterm = 1.0f - g_lut[s * NINT + g_diag[i]];
            const float* y0r = g_Y0 + ((size_t)s * NPOI + i) * DD;
            float* l1r = g_L1 + ((size_t)s * NPOI + i) * DD;
            float* y1r = g_Y1 + ((size_t)s * NPOI + i) * DD;
            #pragma unroll
            for (int ni = 0; ni < 4; ni++) {
                #pragma unroll
                for (int e1 = 0; e1 < 2; e1++) {
                    int d = wn * 32 + ni * 8 + (lane & 3) * 2 + e1;
                    float cf = acc[mi][ni][e2 * 2 + e1] * (1.0f / 63.0f);
                    float l1 = tanhf(idg * (cf + dterm * y0r[d]));
                    l1r[d] = l1;
                    y1r[d] = l1 * idg;
                }
            }
        }
    }
}

// layer-2: gathered 128 rows, K-split 8, single LUT
__global__ __launch_bounds__(256, 2) void gemm2_mma_kernel() {
    const int t = threadIdx.x, wid = t >> 5, lane = t & 31;
    const int pb = blockIdx.x;
    const int s  = blockIdx.y;
    const int kc = blockIdx.z;
    u32* lut = (u32*)(dsm + LUT_OFF);
    int* srows = (int*)(dsm + LUT_OFF + LUT_BYTES);
    const u32 base_u = smem_u32(dsm);

    for (int e = t; e < NINT * 32; e += 256) {
        __half h = __float2half(g_cntf[s * NINT + (e >> 5)]);
        lut[e] = (u32)*(unsigned short*)&h;
    }
    if (t < 128) srows[t] = g_rows[s * NPOS + pb * 128 + t];
    __syncthreads();
    const u32* ml = lut + lane;

    const int pm = t >> 1, ph = t & 1;
    const int bd = t >> 2, bq = t & 3;
    const int kbase = kc * (NPOI / KC);
    const unsigned char* gA = g_bk + (size_t)srows[pm] * NPOI + kbase + ph * 32;
    const __half* gBrow = g_Y1t + ((size_t)s * DD + bd) * NPOI + kbase;
    u32 aaddr[4];
    #pragma unroll
    for (int u2 = 0; u2 < 2; u2++)
        #pragma unroll
        for (int hq = 0; hq < 2; hq++)
            aaddr[u2*2+hq] = swz((u32)(pm * 128 + ph * 64 + u2 * 32 + hq * 16));
    const u32 boff0 = swz((u32)(bd * 128 + bq * 16));
    const u32 boff1 = swz((u32)(bd * 128 + (bq + 4) * 16));

    const int wm = wid & 3, wn = wid >> 2;
    float acc[2][4][4];
    #pragma unroll
    for (int a = 0; a < 2; a++)
        #pragma unroll
        for (int b = 0; b < 4; b++)
            #pragma unroll
            for (int c = 0; c < 4; c++) acc[a][b][c] = 0.0f;

    const u32 arow = (u32)((wm * 32 + (lane & 15)) * 128 + (lane >> 4) * 16);
    const u32 brow = (u32)((wn * 32 + (lane & 15)) * 128 + (lane >> 4) * 16);

    uint4 pa[2];
    pa[0] = *(const uint4*)(gA);  pa[1] = *(const uint4*)(gA + 16);
    CPA16(base_u + 16384 + boff0, gBrow + bq * 8);
    CPA16(base_u + 16384 + boff1, gBrow + (bq + 4) * 8);
    CPCOMMIT();
    conv_store_A1(ml, pa, dsm, aaddr);
    CPWAIT0();
    __syncthreads();

    for (int c = 0; c < NC2; c++) {
        const u32 bufo = (u32)(c & 1) * BUF_BYTES;
        const u32 nbufo = (u32)((c + 1) & 1) * BUF_BYTES;
        if (c + 1 < NC2) {
            int kb = (c + 1) * KT;
            pa[0] = *(const uint4*)(gA + kb);  pa[1] = *(const uint4*)(gA + kb + 16);
            CPA16(base_u + nbufo + 16384 + boff0, gBrow + kb + bq * 8);
            CPA16(base_u + nbufo + 16384 + boff1, gBrow + kb + (bq + 4) * 8);
            CPCOMMIT();
        }
        mma_chunk(base_u + bufo, base_u + bufo + 16384, arow, brow, acc);
        if (c + 1 < NC2) conv_store_A1(ml, pa, dsm + nbufo, aaddr);
        CPWAIT0();
        __syncthreads();
    }

    float* pdst = g_part + ((size_t)kc * NB + s) * NPOS * DD + (size_t)pb * 128 * DD;
    #pragma unroll
    for (int mi = 0; mi < 2; mi++) {
        #pragma unroll
        for (int e2 = 0; e2 < 2; e2++) {
            int pl = wm * 32 + mi * 16 + (lane >> 2) + e2 * 8;
            #pragma unroll
            for (int ni = 0; ni < 4; ni++) {
                int d = wn * 32 + ni * 8 + (lane & 3) * 2;
                *(float2*)(pdst + pl * DD + d) =
                    make_float2(acc[mi][ni][e2 * 2], acc[mi][ni][e2 * 2 + 1]);
            }
        }
    }
}

__global__ __launch_bounds__(256) void finalize_kernel(const float* __restrict__ poi,
                                                       float* __restrict__ out) {
    int e = blockIdx.x * 256 + threadIdx.x;
    int d = e & 63, pl = e >> 6, pos = pl & 255, s = pl >> 8;
    int r = g_rows[s * NPOS + pos];
    float acc = 0.0f;
    #pragma unroll
    for (int kc = 0; kc < KC; kc++)
        acc += g_part[(((size_t)kc * NB + s) * NPOS + pos) * DD + d];
    acc *= (1.0f / 63.0f);
    float idg = g_invdeg[s * NPOI + r];
    float dterm = 1.0f - g_lut[s * NINT + g_diag[r]];
    size_t off = ((size_t)s * NPOI + r) * DD + d;
    float l2 = tanhf(idg * (acc + dterm * g_Y1[off]));
    float v = 8.0f * (poi[(size_t)(r + 1) * DD + d] + g_L1[off] + l2);
    int day = pos >> 6, l = pos & 63;
    out[(((size_t)(s * DAYS + day)) * LL + l) * DD + d] = v;
}

extern "C" void kernel_launch(void* const* d_in, const int* in_sizes, int n_in,
                              void* d_out, int out_size) {
    (void)in_sizes; (void)n_in; (void)out_size;
    const float* poi  = (const float*)d_in[0];
    const float* dist = (const float*)d_in[1];
    const int*   seq  = (const int*)d_in[2];
    const int*   ids  = (const int*)d_in[3];
    float* out = (float*)d_out;

    cudaFuncSetAttribute(gemm1_mma_kernel, cudaFuncAttributeMaxDynamicSharedMemorySize, SMEM_G);
    cudaFuncSetAttribute(gemm2_mma_kernel, cudaFuncAttributeMaxDynamicSharedMemorySize, SMEM_G2);

    buckhist_setup_kernel<<<NPOI + 1, 256>>>(dist, seq, ids);
    deg_kernel           <<<NPOI / 256, 256>>>();
    y0t_kernel           <<<dim3(NPOI / 64, NB), 256>>>(poi);
    gemm1_mma_kernel     <<<dim3(NPOI / MT, NB), 256, SMEM_G>>>(); // launch 3 (ncu slot)
    y1t_kernel           <<<dim3(NPOI / 64, NB), 256>>>();
    gemm2_mma_kernel     <<<dim3(2, NB, KC), 256, SMEM_G2>>>();
    finalize_kernel      <<<(NB * NPOS * DD) / 256, 256>>>(poi, out);
}

// round 12
// speedup vs baseline: 1.0359x; 1.0359x over previous
#include <cuda_runtime.h>
#include <cuda_fp16.h>
#include <cstdint>
#include <cstddef>

#define NPOI 4096
#define DD   64
#define NB   8
#define DAYS 4
#define LL   64
#define NDROWS 32
#define NPOS   256
#define NINT 101
#define KC   8
#define KS   2                     /* gemm1 K-split */
#define MT   128
#define KT   64
#define NC1  (NPOI/KS/KT)          /* 32 chunks per gemm1 CTA */
#define NC2  (NPOI/KC/KT)
#define BUF_BYTES 24576
#define LUT_OFF   (2*BUF_BYTES)
#define LUT_BYTES (NINT*32*4)
#define SMEM_G    (LUT_OFF + LUT_BYTES)
#define SMEM_G2   (SMEM_G + 512)

typedef unsigned long long u64;
typedef unsigned int u32;

__device__ __align__(16) unsigned char g_bk[(size_t)NPOI * NPOI];
__device__ unsigned char g_diag[NPOI];
__device__ int   g_histT[NINT * NPOI];
__device__ float g_lut[NB * NINT];
__device__ float g_cntf[NB * NINT];
__device__ float g_invdeg[NB * NPOI];
__device__ int   g_rows[NB * NPOS];
__device__ float g_Y0[(size_t)NB * NPOI * DD];
__device__ float g_L1[(size_t)NB * NPOI * DD];
__device__ float g_Y1[(size_t)NB * NPOI * DD];
__device__ __align__(16) __half g_Yt[(size_t)NB * DD * NPOI];
__device__ __align__(16) __half g_Y1t[(size_t)NB * DD * NPOI];
__device__ float g_part[(size_t)KC * NB * NPOS * DD];
__device__ float g_c1[(size_t)KS * NB * NPOI * DD];   /* gemm1 K-split partials */

__device__ __forceinline__ u32 smem_u32(const void* p) {
    u32 a; asm("{ .reg .u64 t; cvta.to.shared.u64 t, %1; cvt.u32.u64 %0, t; }" : "=r"(a) : "l"(p));
    return a;
}
__device__ __forceinline__ u32 swz(u32 o) { return o ^ ((o >> 3) & 0x70); }
__device__ __forceinline__ void ldsm4(u32& r0, u32& r1, u32& r2, u32& r3, u32 a) {
    asm volatile("ldmatrix.sync.aligned.m8n8.x4.shared.b16 {%0,%1,%2,%3}, [%4];"
        : "=r"(r0), "=r"(r1), "=r"(r2), "=r"(r3) : "r"(a));
}
__device__ __forceinline__ void mma16816(float* c, const u32* a, u32 b0, u32 b1) {
    asm volatile("mma.sync.aligned.m16n8k16.row.col.f32.f16.f16.f32 "
        "{%0,%1,%2,%3}, {%4,%5,%6,%7}, {%8,%9}, {%0,%1,%2,%3};"
        : "+f"(c[0]), "+f"(c[1]), "+f"(c[2]), "+f"(c[3])
        : "r"(a[0]), "r"(a[1]), "r"(a[2]), "r"(a[3]), "r"(b0), "r"(b1));
}
#define CPA16(dst, src) asm volatile("cp.async.cg.shared.global [%0], [%1], 16;" :: "r"(dst), "l"(src))
#define CPCOMMIT()      asm volatile("cp.async.commit_group;")
#define CPWAIT0()       asm volatile("cp.async.wait_group 0;")

__device__ __forceinline__ void conv_store_A1(const u32* ml, const uint4* pa,
                                              char* Ab, const u32* aaddr) {
    #pragma unroll
    for (int u2 = 0; u2 < 2; u2++) {
        union { uint4 v; unsigned char b[16]; } q; q.v = pa[u2];
        #pragma unroll
        for (int hq = 0; hq < 2; hq++) {
            uint4 o;
            o.x = ml[q.b[hq*8+0]*32] | (ml[q.b[hq*8+1]*32] << 16);
            o.y = ml[q.b[hq*8+2]*32] | (ml[q.b[hq*8+3]*32] << 16);
            o.z = ml[q.b[hq*8+4]*32] | (ml[q.b[hq*8+5]*32] << 16);
            o.w = ml[q.b[hq*8+6]*32] | (ml[q.b[hq*8+7]*32] << 16);
            *(uint4*)(Ab + aaddr[u2*2+hq]) = o;
        }
    }
}

__device__ __forceinline__ void mma_chunk(u32 Ab_u, u32 Bb_u, u32 arow, u32 brow,
                                          float (&acc)[2][4][4]) {
    #pragma unroll
    for (int kk = 0; kk < 4; kk++) {
        const u32 kby = (u32)(kk * 32);
        u32 afr[2][4];
        #pragma unroll
        for (int mi = 0; mi < 2; mi++)
            ldsm4(afr[mi][0], afr[mi][1], afr[mi][2], afr[mi][3],
                  Ab_u + swz(arow + mi * 16 * 128 + kby));
        #pragma unroll
        for (int ni2 = 0; ni2 < 2; ni2++) {
            u32 r0, r1, r2, r3;
            ldsm4(r0, r1, r2, r3, Bb_u + swz(brow + ni2 * 16 * 128 + kby));
            #pragma unroll
            for (int mi = 0; mi < 2; mi++) {
                mma16816(acc[mi][ni2 * 2],     afr[mi], r0, r2);
                mma16816(acc[mi][ni2 * 2 + 1], afr[mi], r1, r3);
            }
        }
    }
}

// fused: blocks 0..4095 = bucket+hist; block 4096 = per-sample setup
__global__ __launch_bounds__(256) void buckhist_setup_kernel(const float* __restrict__ dist,
                                                             const int* __restrict__ seq,
                                                             const int* __restrict__ ids) {
    __shared__ int sh[NINT];
    __shared__ int sord[NDROWS];
    __shared__ int scnt[NB][NINT];
    int t = threadIdx.x;
    if (blockIdx.x < NPOI) {
        int i = blockIdx.x;
        if (t < NINT) sh[t] = 0;
        __syncthreads();
        const float* row = dist + (size_t)i * NPOI;
        union { uint4 v; unsigned char b[16]; } o;
        #pragma unroll
        for (int v = 0; v < 4; v++) {
            float4 f = *(const float4*)(row + t * 16 + v * 4);
            o.b[v*4+0] = (unsigned char)min(100, (int)floorf(f.x * 2.0f) + 1);
            o.b[v*4+1] = (unsigned char)min(100, (int)floorf(f.y * 2.0f) + 1);
            o.b[v*4+2] = (unsigned char)min(100, (int)floorf(f.z * 2.0f) + 1);
            o.b[v*4+3] = (unsigned char)min(100, (int)floorf(f.w * 2.0f) + 1);
        }
        #pragma unroll
        for (int m = 0; m < 16; m++) atomicAdd(&sh[o.b[m]], 1);
        *(uint4*)(g_bk + (size_t)i * NPOI + t * 16) = o.v;
        if ((i >> 4) == t) g_diag[i] = o.b[i & 15];
        __syncthreads();
        if (t < NINT) g_histT[t * NPOI + i] = sh[t];
        return;
    }
    if (t < NDROWS) {
        int my = ids[t], pos = 0;
        for (int q = 0; q < NDROWS; q++) {
            int v = ids[q];
            if (v < my || (v == my && q < t)) pos++;
        }
        sord[pos] = t;
    }
    for (int e = t; e < NB * NINT; e += 256) (&scnt[0][0])[e] = 0;
    __syncthreads();
    for (int e = t; e < NB * NPOS; e += 256) {
        int s = e >> 8, pos = e & 255, day = pos >> 6, l = pos & 63;
        g_rows[e] = seq[sord[s * DAYS + day] * LL + l] - 1;
    }
    for (int e = t; e < NB * (LL - 1); e += 256) {
        int s = e / (LL - 1), tt = e % (LL - 1);
        int lrow = sord[s * DAYS + (DAYS - 1)];
        int a = seq[lrow * LL + tt] - 1;
        int b = seq[lrow * LL + tt + 1] - 1;
        float dv = dist[(size_t)a * NPOI + b];
        int idx = (int)ceilf(dv * 2.0f);
        idx = idx < 0 ? 0 : (idx > 100 ? 100 : idx);
        atomicAdd(&scnt[s][idx], 1);
    }
    __syncthreads();
    for (int e = t; e < NB * NINT; e += 256) {
        int cv = (&scnt[0][0])[e];
        g_lut[e]  = (float)cv / 63.0f;
        g_cntf[e] = (float)cv;
    }
}

__global__ __launch_bounds__(256) void deg_kernel() {
    __shared__ float lc[NB][NINT];
    int t = threadIdx.x;
    for (int e = t; e < NB * NINT; e += 256) (&lc[0][0])[e] = g_lut[e];
    __syncthreads();
    int i = blockIdx.x * 256 + t;
    int dg = g_diag[i];
    float sums[NB];
    #pragma unroll
    for (int s = 0; s < NB; s++) sums[s] = 1.0f - lc[s][dg];
    #pragma unroll 101
    for (int k = 0; k < NINT; k++) {
        float h = (float)g_histT[k * NPOI + i];
        #pragma unroll
        for (int s = 0; s < NB; s++) sums[s] += lc[s][k] * h;
    }
    #pragma unroll
    for (int s = 0; s < NB; s++)
        g_invdeg[s * NPOI + i] = 1.0f / sqrtf(fmaxf(sums[s], 1e-24f));
}

__global__ __launch_bounds__(256) void y0t_kernel(const float* __restrict__ poi) {
    __shared__ float ts[64][65];
    int s = blockIdx.y, jbase = blockIdx.x * 64, t = threadIdx.x;
    #pragma unroll
    for (int r = 0; r < 16; r++) {
        int idx = r * 256 + t;
        int jl = idx >> 6, d = idx & 63;
        int j = jbase + jl;
        float y = poi[(size_t)(j + 1) * DD + d] * g_invdeg[s * NPOI + j];
        g_Y0[((size_t)s * NPOI + j) * DD + d] = y;
        ts[jl][d] = y;
    }
    __syncthreads();
    #pragma unroll
    for (int r = 0; r < 16; r++) {
        int idx = r * 256 + t;
        int d = idx >> 6, jl = idx & 63;
        g_Yt[((size_t)s * DD + d) * NPOI + jbase + jl] = __float2half(ts[jl][d]);
    }
}

// sum K-split partials, /63, diag fix, tanh -> L1, Y1, and transposed fp16 Y1t
__global__ __launch_bounds__(256) void l1fin_kernel() {
    __shared__ float ts[64][65];
    int s = blockIdx.y, jbase = blockIdx.x * 64, t = threadIdx.x;
    #pragma unroll
    for (int r = 0; r < 16; r++) {
        int idx = r * 256 + t;
        int jl = idx >> 6, d = idx & 63;
        int j = jbase + jl;
        size_t off = ((size_t)s * NPOI + j) * DD + d;
        float cf = (g_c1[off] + g_c1[(size_t)NB * NPOI * DD + off]) * (1.0f / 63.0f);
        float idg = g_invdeg[s * NPOI + j];
        float dterm = 1.0f - g_lut[s * NINT + g_diag[j]];
        float l1 = tanhf(idg * (cf + dterm * g_Y0[off]));
        g_L1[off] = l1;
        float y1 = l1 * idg;
        g_Y1[off] = y1;
        ts[jl][d] = y1;
    }
    __syncthreads();
    #pragma unroll
    for (int r = 0; r < 16; r++) {
        int idx = r * 256 + t;
        int d = idx >> 6, jl = idx & 63;
        g_Y1t[((size_t)s * DD + d) * NPOI + jbase + jl] = __float2half(ts[jl][d]);
    }
}

extern __shared__ __align__(1024) char dsm[];

// layer-1: MT=128, 256 thr, K-split 2 -> 512 CTAs, occ 3; writes fp32 partials
__global__ __launch_bounds__(256, 3) void gemm1_mma_kernel() {
    const int t = threadIdx.x, wid = t >> 5, lane = t & 31;
    const int s = blockIdx.y;
    const int kc = blockIdx.z;
    const int rowbase = blockIdx.x * MT;
    const int kbase = kc * (NPOI / KS);
    u32* lut = (u32*)(dsm + LUT_OFF);
    const u32 base_u = smem_u32(dsm);

    for (int e = t; e < NINT * 32; e += 256) {
        __half h = __float2half(g_cntf[s * NINT + (e >> 5)]);
        lut[e] = (u32)*(unsigned short*)&h;
    }
    __syncthreads();
    const u32* ml = lut + lane;

    const int pm = t >> 1, ph = t & 1;
    const int bd = t >> 2, bq = t & 3;
    const unsigned char* gA = g_bk + (size_t)(rowbase + pm) * NPOI + kbase + ph * 32;
    const __half* gBrow = g_Yt + ((size_t)s * DD + bd) * NPOI + kbase;
    u32 aaddr[4];
    #pragma unroll
    for (int u2 = 0; u2 < 2; u2++)
        #pragma unroll
        for (int hq = 0; hq < 2; hq++)
            aaddr[u2*2+hq] = swz((u32)(pm * 128 + ph * 64 + u2 * 32 + hq * 16));
    const u32 boff0 = swz((u32)(bd * 128 + bq * 16));
    const u32 boff1 = swz((u32)(bd * 128 + (bq + 4) * 16));

    const int wm = wid & 3, wn = wid >> 2;
    float acc[2][4][4];
    #pragma unroll
    for (int a = 0; a < 2; a++)
        #pragma unroll
        for (int b = 0; b < 4; b++)
            #pragma unroll
            for (int c = 0; c < 4; c++) acc[a][b][c] = 0.0f;

    const u32 arow = (u32)((wm * 32 + (lane & 15)) * 128 + (lane >> 4) * 16);
    const u32 brow = (u32)((wn * 32 + (lane & 15)) * 128 + (lane >> 4) * 16);

    uint4 pa[2];
    pa[0] = *(const uint4*)(gA);  pa[1] = *(const uint4*)(gA + 16);
    CPA16(base_u + 16384 + boff0, gBrow + bq * 8);
    CPA16(base_u + 16384 + boff1, gBrow + (bq + 4) * 8);
    CPCOMMIT();
    conv_store_A1(ml, pa, dsm, aaddr);
    CPWAIT0();
    __syncthreads();

    for (int c = 0; c < NC1; c++) {
        const u32 bufo = (u32)(c & 1) * BUF_BYTES;
        const u32 nbufo = (u32)((c + 1) & 1) * BUF_BYTES;
        if (c + 1 < NC1) {
            int kb = (c + 1) * KT;
            pa[0] = *(const uint4*)(gA + kb);  pa[1] = *(const uint4*)(gA + kb + 16);
            CPA16(base_u + nbufo + 16384 + boff0, gBrow + kb + bq * 8);
            CPA16(base_u + nbufo + 16384 + boff1, gBrow + kb + (bq + 4) * 8);
            CPCOMMIT();
        }
        mma_chunk(base_u + bufo, base_u + bufo + 16384, arow, brow, acc);
        if (c + 1 < NC1) conv_store_A1(ml, pa, dsm + nbufo, aaddr);
        CPWAIT0();
        __syncthreads();
    }

    // write raw fp32 partials
    float* pdst = g_c1 + ((size_t)kc * NB + s) * NPOI * DD + (size_t)rowbase * DD;
    #pragma unroll
    for (int mi = 0; mi < 2; mi++) {
        #pragma unroll
        for (int e2 = 0; e2 < 2; e2++) {
            int pl = wm * 32 + mi * 16 + (lane >> 2) + e2 * 8;
            #pragma unroll
            for (int ni = 0; ni < 4; ni++) {
                int d = wn * 32 + ni * 8 + (lane & 3) * 2;
                *(float2*)(pdst + pl * DD + d) =
                    make_float2(acc[mi][ni][e2 * 2], acc[mi][ni][e2 * 2 + 1]);
            }
        }
    }
}

// layer-2: gathered 128 rows, K-split 8, single LUT
__global__ __launch_bounds__(256, 2) void gemm2_mma_kernel() {
    const int t = threadIdx.x, wid = t >> 5, lane = t & 31;
    const int pb = blockIdx.x;
    const int s  = blockIdx.y;
    const int kc = blockIdx.z;
    u32* lut = (u32*)(dsm + LUT_OFF);
    int* srows = (int*)(dsm + LUT_OFF + LUT_BYTES);
    const u32 base_u = smem_u32(dsm);

    for (int e = t; e < NINT * 32; e += 256) {
        __half h = __float2half(g_cntf[s * NINT + (e >> 5)]);
        lut[e] = (u32)*(unsigned short*)&h;
    }
    if (t < 128) srows[t] = g_rows[s * NPOS + pb * 128 + t];
    __syncthreads();
    const u32* ml = lut + lane;

    const int pm = t >> 1, ph = t & 1;
    const int bd = t >> 2, bq = t & 3;
    const int kbase = kc * (NPOI / KC);
    const unsigned char* gA = g_bk + (size_t)srows[pm] * NPOI + kbase + ph * 32;
    const __half* gBrow = g_Y1t + ((size_t)s * DD + bd) * NPOI + kbase;
    u32 aaddr[4];
    #pragma unroll
    for (int u2 = 0; u2 < 2; u2++)
        #pragma unroll
        for (int hq = 0; hq < 2; hq++)
            aaddr[u2*2+hq] = swz((u32)(pm * 128 + ph * 64 + u2 * 32 + hq * 16));
    const u32 boff0 = swz((u32)(bd * 128 + bq * 16));
    const u32 boff1 = swz((u32)(bd * 128 + (bq + 4) * 16));

    const int wm = wid & 3, wn = wid >> 2;
    float acc[2][4][4];
    #pragma unroll
    for (int a = 0; a < 2; a++)
        #pragma unroll
        for (int b = 0; b < 4; b++)
            #pragma unroll
            for (int c = 0; c < 4; c++) acc[a][b][c] = 0.0f;

    const u32 arow = (u32)((wm * 32 + (lane & 15)) * 128 + (lane >> 4) * 16);
    const u32 brow = (u32)((wn * 32 + (lane & 15)) * 128 + (lane >> 4) * 16);

    uint4 pa[2];
    pa[0] = *(const uint4*)(gA);  pa[1] = *(const uint4*)(gA + 16);
    CPA16(base_u + 16384 + boff0, gBrow + bq * 8);
    CPA16(base_u + 16384 + boff1, gBrow + (bq + 4) * 8);
    CPCOMMIT();
    conv_store_A1(ml, pa, dsm, aaddr);
    CPWAIT0();
    __syncthreads();

    for (int c = 0; c < NC2; c++) {
        const u32 bufo = (u32)(c & 1) * BUF_BYTES;
        const u32 nbufo = (u32)((c + 1) & 1) * BUF_BYTES;
        if (c + 1 < NC2) {
            int kb = (c + 1) * KT;
            pa[0] = *(const uint4*)(gA + kb);  pa[1] = *(const uint4*)(gA + kb + 16);
            CPA16(base_u + nbufo + 16384 + boff0, gBrow + kb + bq * 8);
            CPA16(base_u + nbufo + 16384 + boff1, gBrow + kb + (bq + 4) * 8);
            CPCOMMIT();
        }
        mma_chunk(base_u + bufo, base_u + bufo + 16384, arow, brow, acc);
        if (c + 1 < NC2) conv_store_A1(ml, pa, dsm + nbufo, aaddr);
        CPWAIT0();
        __syncthreads();
    }

    float* pdst = g_part + ((size_t)kc * NB + s) * NPOS * DD + (size_t)pb * 128 * DD;
    #pragma unroll
    for (int mi = 0; mi < 2; mi++) {
        #pragma unroll
        for (int e2 = 0; e2 < 2; e2++) {
            int pl = wm * 32 + mi * 16 + (lane >> 2) + e2 * 8;
            #pragma unroll
            for (int ni = 0; ni < 4; ni++) {
                int d = wn * 32 + ni * 8 + (lane & 3) * 2;
                *(float2*)(pdst + pl * DD + d) =
                    make_float2(acc[mi][ni][e2 * 2], acc[mi][ni][e2 * 2 + 1]);
            }
        }
    }
}

__global__ __launch_bounds__(256) void finalize_kernel(const float* __restrict__ poi,
                                                       float* __restrict__ out) {
    int e = blockIdx.x * 256 + threadIdx.x;
    int d = e & 63, pl = e >> 6, pos = pl & 255, s = pl >> 8;
    int r = g_rows[s * NPOS + pos];
    float acc = 0.0f;
    #pragma unroll
    for (int kc = 0; kc < KC; kc++)
        acc += g_part[(((size_t)kc * NB + s) * NPOS + pos) * DD + d];
    acc *= (1.0f / 63.0f);
    float idg = g_invdeg[s * NPOI + r];
    float dterm = 1.0f - g_lut[s * NINT + g_diag[r]];
    size_t off = ((size_t)s * NPOI + r) * DD + d;
    float l2 = tanhf(idg * (acc + dterm * g_Y1[off]));
    float v = 8.0f * (poi[(size_t)(r + 1) * DD + d] + g_L1[off] + l2);
    int day = pos >> 6, l = pos & 63;
    out[(((size_t)(s * DAYS + day)) * LL + l) * DD + d] = v;
}

extern "C" void kernel_launch(void* const* d_in, const int* in_sizes, int n_in,
                              void* d_out, int out_size) {
    (void)in_sizes; (void)n_in; (void)out_size;
    const float* poi  = (const float*)d_in[0];
    const float* dist = (const float*)d_in[1];
    const int*   seq  = (const int*)d_in[2];
    const int*   ids  = (const int*)d_in[3];
    float* out = (float*)d_out;

    cudaFuncSetAttribute(gemm1_mma_kernel, cudaFuncAttributeMaxDynamicSharedMemorySize, SMEM_G);
    cudaFuncSetAttribute(gemm2_mma_kernel, cudaFuncAttributeMaxDynamicSharedMemorySize, SMEM_G2);

    buckhist_setup_kernel<<<NPOI + 1, 256>>>(dist, seq, ids);
    deg_kernel           <<<NPOI / 256, 256>>>();
    y0t_kernel           <<<dim3(NPOI / 64, NB), 256>>>(poi);
    gemm1_mma_kernel     <<<dim3(NPOI / MT, NB, KS), 256, SMEM_G>>>(); // launch 3 (ncu slot)
    l1fin_kernel         <<<dim3(NPOI / 64, NB), 256>>>();
    gemm2_mma_kernel     <<<dim3(2, NB, KC), 256, SMEM_G2>>>();
    finalize_kernel      <<<(NB * NPOS * DD) / 256, 256>>>(poi, out);
}

// round 13
// speedup vs baseline: 1.0379x; 1.0019x over previous
#include <cuda_runtime.h>
#include <cuda_fp16.h>
#include <cstdint>
#include <cstddef>

#define NPOI 4096
#define DD   64
#define NB   8
#define DAYS 4
#define LL   64
#define NDROWS 32
#define NPOS   256
#define NINT 101
#define KC   8
#define KS   2
#define MT   128
#define KT   64
#define NC1  (NPOI/KS/KT)
#define NC2  (NPOI/KC/KT)
#define BUF_BYTES 24576
#define LUT_OFF   (2*BUF_BYTES)
#define LUT_BYTES (NINT*32*4)
#define SMEM_G    (LUT_OFF + 2*LUT_BYTES)   /* 75008; x3 = 225KB fits 228KB */
#define SMEM_G2   (SMEM_G + 512)

typedef unsigned long long u64;
typedef unsigned int u32;

__device__ __align__(16) unsigned char g_bk[(size_t)NPOI * NPOI];
__device__ unsigned char g_diag[NPOI];
__device__ float g_lut[NB * NINT];
__device__ float g_cntf[NB * NINT];
__device__ float g_invdeg[NB * NPOI];
__device__ int   g_rows[NB * NPOS];
__device__ float g_Y0[(size_t)NB * NPOI * DD];
__device__ float g_L1[(size_t)NB * NPOI * DD];
__device__ float g_Y1[(size_t)NB * NPOI * DD];
__device__ __align__(16) __half g_Yt[(size_t)NB * DD * NPOI];
__device__ __align__(16) __half g_Y1t[(size_t)NB * DD * NPOI];
__device__ float g_part[(size_t)KC * NB * NPOS * DD];
__device__ float g_c1[(size_t)KS * NB * NPOI * DD];

__device__ __forceinline__ u32 smem_u32(const void* p) {
    u32 a; asm("{ .reg .u64 t; cvta.to.shared.u64 t, %1; cvt.u32.u64 %0, t; }" : "=r"(a) : "l"(p));
    return a;
}
__device__ __forceinline__ u32 swz(u32 o) { return o ^ ((o >> 3) & 0x70); }
__device__ __forceinline__ void ldsm4(u32& r0, u32& r1, u32& r2, u32& r3, u32 a) {
    asm volatile("ldmatrix.sync.aligned.m8n8.x4.shared.b16 {%0,%1,%2,%3}, [%4];"
        : "=r"(r0), "=r"(r1), "=r"(r2), "=r"(r3) : "r"(a));
}
__device__ __forceinline__ void mma16816(float* c, const u32* a, u32 b0, u32 b1) {
    asm volatile("mma.sync.aligned.m16n8k16.row.col.f32.f16.f16.f32 "
        "{%0,%1,%2,%3}, {%4,%5,%6,%7}, {%8,%9}, {%0,%1,%2,%3};"
        : "+f"(c[0]), "+f"(c[1]), "+f"(c[2]), "+f"(c[3])
        : "r"(a[0]), "r"(a[1]), "r"(a[2]), "r"(a[3]), "r"(b0), "r"(b1));
}
#define CPA16(dst, src) asm volatile("cp.async.cg.shared.global [%0], [%1], 16;" :: "r"(dst), "l"(src))
#define CPCOMMIT()      asm volatile("cp.async.commit_group;")
#define CPWAIT0()       asm volatile("cp.async.wait_group 0;")

// two-table LUT convert: no shifts (lo has bits, hi has bits<<16)
__device__ __forceinline__ void conv_store_A(const u32* lo, const u32* hi,
                                             const uint4* pa, char* Ab, const u32* aaddr) {
    #pragma unroll
    for (int u2 = 0; u2 < 2; u2++) {
        union { uint4 v; unsigned char b[16]; } q; q.v = pa[u2];
        #pragma unroll
        for (int hq = 0; hq < 2; hq++) {
            uint4 o;
            o.x = lo[q.b[hq*8+0]*32] | hi[q.b[hq*8+1]*32];
            o.y = lo[q.b[hq*8+2]*32] | hi[q.b[hq*8+3]*32];
            o.z = lo[q.b[hq*8+4]*32] | hi[q.b[hq*8+5]*32];
            o.w = lo[q.b[hq*8+6]*32] | hi[q.b[hq*8+7]*32];
            *(uint4*)(Ab + aaddr[u2*2+hq]) = o;
        }
    }
}

__device__ __forceinline__ void mma_chunk(u32 Ab_u, u32 Bb_u, u32 arow, u32 brow,
                                          float (&acc)[2][4][4]) {
    #pragma unroll
    for (int kk = 0; kk < 4; kk++) {
        const u32 kby = (u32)(kk * 32);
        u32 afr[2][4];
        #pragma unroll
        for (int mi = 0; mi < 2; mi++)
            ldsm4(afr[mi][0], afr[mi][1], afr[mi][2], afr[mi][3],
                  Ab_u + swz(arow + mi * 16 * 128 + kby));
        #pragma unroll
        for (int ni2 = 0; ni2 < 2; ni2++) {
            u32 r0, r1, r2, r3;
            ldsm4(r0, r1, r2, r3, Bb_u + swz(brow + ni2 * 16 * 128 + kby));
            #pragma unroll
            for (int mi = 0; mi < 2; mi++) {
                mma16816(acc[mi][ni2 * 2],     afr[mi], r0, r2);
                mma16816(acc[mi][ni2 * 2 + 1], afr[mi], r1, r3);
            }
        }
    }
}

// per-sample setup: runs FIRST (only needs dist/seq/ids)
__global__ __launch_bounds__(256) void setup_kernel(const float* __restrict__ dist,
                                                    const int* __restrict__ seq,
                                                    const int* __restrict__ ids) {
    __shared__ int sord[NDROWS];
    __shared__ int scnt[NB][NINT];
    int t = threadIdx.x;
    if (t < NDROWS) {
        int my = ids[t], pos = 0;
        for (int q = 0; q < NDROWS; q++) {
            int v = ids[q];
            if (v < my || (v == my && q < t)) pos++;
        }
        sord[pos] = t;
    }
    for (int e = t; e < NB * NINT; e += 256) (&scnt[0][0])[e] = 0;
    __syncthreads();
    for (int e = t; e < NB * NPOS; e += 256) {
        int s = e >> 8, pos = e & 255, day = pos >> 6, l = pos & 63;
        g_rows[e] = seq[sord[s * DAYS + day] * LL + l] - 1;
    }
    for (int e = t; e < NB * (LL - 1); e += 256) {
        int s = e / (LL - 1), tt = e % (LL - 1);
        int lrow = sord[s * DAYS + (DAYS - 1)];
        int a = seq[lrow * LL + tt] - 1;
        int b = seq[lrow * LL + tt + 1] - 1;
        float dv = dist[(size_t)a * NPOI + b];
        int idx = (int)ceilf(dv * 2.0f);
        idx = idx < 0 ? 0 : (idx > 100 ? 100 : idx);
        atomicAdd(&scnt[s][idx], 1);
    }
    __syncthreads();
    for (int e = t; e < NB * NINT; e += 256) {
        int cv = (&scnt[0][0])[e];
        g_lut[e]  = (float)cv / 63.0f;
        g_cntf[e] = (float)cv;
    }
}

// bucket + per-warp hist + fused per-sample degree (no histT, no deg kernel)
__global__ __launch_bounds__(256) void buckhist_kernel(const float* __restrict__ dist) {
    __shared__ int sh[8][NINT + 3];
    __shared__ int hist[NINT];
    __shared__ float slut[NB * NINT];
    __shared__ int sdiag;
    int i = blockIdx.x, t = threadIdx.x, wid = t >> 5, lane = t & 31;
    for (int e = t; e < 8 * (NINT + 3); e += 256) (&sh[0][0])[e] = 0;
    for (int e = t; e < NB * NINT; e += 256) slut[e] = g_lut[e];
    __syncthreads();
    const float* row = dist + (size_t)i * NPOI;
    union { uint4 v; unsigned char b[16]; } o;
    #pragma unroll
    for (int v = 0; v < 4; v++) {
        float4 f = *(const float4*)(row + t * 16 + v * 4);
        o.b[v*4+0] = (unsigned char)min(100, (int)floorf(f.x * 2.0f) + 1);
        o.b[v*4+1] = (unsigned char)min(100, (int)floorf(f.y * 2.0f) + 1);
        o.b[v*4+2] = (unsigned char)min(100, (int)floorf(f.z * 2.0f) + 1);
        o.b[v*4+3] = (unsigned char)min(100, (int)floorf(f.w * 2.0f) + 1);
    }
    #pragma unroll
    for (int m = 0; m < 16; m++) atomicAdd(&sh[wid][o.b[m]], 1);
    *(uint4*)(g_bk + (size_t)i * NPOI + t * 16) = o.v;
    if ((i >> 4) == t) { g_diag[i] = o.b[i & 15]; sdiag = o.b[i & 15]; }
    __syncthreads();
    if (t < NINT) {
        int h = 0;
        #pragma unroll
        for (int w = 0; w < 8; w++) h += sh[w][t];
        hist[t] = h;
    }
    __syncthreads();
    {   // warp wid = sample wid
        float part = 0.0f;
        for (int k = lane; k < NINT; k += 32)
            part += slut[wid * NINT + k] * (float)hist[k];
        #pragma unroll
        for (int off = 16; off > 0; off >>= 1)
            part += __shfl_down_sync(0xffffffffu, part, off);
        if (lane == 0) {
            float sum = part + 1.0f - slut[wid * NINT + sdiag];
            g_invdeg[wid * NPOI + i] = 1.0f / sqrtf(fmaxf(sum, 1e-24f));
        }
    }
}

__global__ __launch_bounds__(256) void y0t_kernel(const float* __restrict__ poi) {
    __shared__ float ts[64][65];
    int s = blockIdx.y, jbase = blockIdx.x * 64, t = threadIdx.x;
    #pragma unroll
    for (int r = 0; r < 16; r++) {
        int idx = r * 256 + t;
        int jl = idx >> 6, d = idx & 63;
        int j = jbase + jl;
        float y = poi[(size_t)(j + 1) * DD + d] * g_invdeg[s * NPOI + j];
        g_Y0[((size_t)s * NPOI + j) * DD + d] = y;
        ts[jl][d] = y;
    }
    __syncthreads();
    #pragma unroll
    for (int r = 0; r < 16; r++) {
        int idx = r * 256 + t;
        int d = idx >> 6, jl = idx & 63;
        g_Yt[((size_t)s * DD + d) * NPOI + jbase + jl] = __float2half(ts[jl][d]);
    }
}

// sum K-split partials, /63, diag fix, tanh -> L1, Y1, transposed fp16 Y1t
__global__ __launch_bounds__(256) void l1fin_kernel() {
    __shared__ float ts[64][65];
    int s = blockIdx.y, jbase = blockIdx.x * 64, t = threadIdx.x;
    #pragma unroll
    for (int r = 0; r < 16; r++) {
        int idx = r * 256 + t;
        int jl = idx >> 6, d = idx & 63;
        int j = jbase + jl;
        size_t off = ((size_t)s * NPOI + j) * DD + d;
        float cf = (g_c1[off] + g_c1[(size_t)NB * NPOI * DD + off]) * (1.0f / 63.0f);
        float idg = g_invdeg[s * NPOI + j];
        float dterm = 1.0f - g_lut[s * NINT + g_diag[j]];
        float l1 = tanhf(idg * (cf + dterm * g_Y0[off]));
        g_L1[off] = l1;
        float y1 = l1 * idg;
        g_Y1[off] = y1;
        ts[jl][d] = y1;
    }
    __syncthreads();
    #pragma unroll
    for (int r = 0; r < 16; r++) {
        int idx = r * 256 + t;
        int d = idx >> 6, jl = idx & 63;
        g_Y1t[((size_t)s * DD + d) * NPOI + jbase + jl] = __float2half(ts[jl][d]);
    }
}

extern __shared__ __align__(1024) char dsm[];

// layer-1: MT=128, K-split 2 -> 512 CTAs, occ 3, two-table LUT
__global__ __launch_bounds__(256, 3) void gemm1_mma_kernel() {
    const int t = threadIdx.x, wid = t >> 5, lane = t & 31;
    const int s = blockIdx.y;
    const int kc = blockIdx.z;
    const int rowbase = blockIdx.x * MT;
    const int kbase = kc * (NPOI / KS);
    u32* lutlo = (u32*)(dsm + LUT_OFF);
    u32* luthi = (u32*)(dsm + LUT_OFF + LUT_BYTES);
    const u32 base_u = smem_u32(dsm);

    for (int e = t; e < NINT * 32; e += 256) {
        __half h = __float2half(g_cntf[s * NINT + (e >> 5)]);
        u32 bits = (u32)*(unsigned short*)&h;
        lutlo[e] = bits;
        luthi[e] = bits << 16;
    }
    __syncthreads();
    const u32* mlo = lutlo + lane;
    const u32* mhi = luthi + lane;

    const int pm = t >> 1, ph = t & 1;
    const int bd = t >> 2, bq = t & 3;
    const unsigned char* gA = g_bk + (size_t)(rowbase + pm) * NPOI + kbase + ph * 32;
    const __half* gBrow = g_Yt + ((size_t)s * DD + bd) * NPOI + kbase;
    u32 aaddr[4];
    #pragma unroll
    for (int u2 = 0; u2 < 2; u2++)
        #pragma unroll
        for (int hq = 0; hq < 2; hq++)
            aaddr[u2*2+hq] = swz((u32)(pm * 128 + ph * 64 + u2 * 32 + hq * 16));
    const u32 boff0 = swz((u32)(bd * 128 + bq * 16));
    const u32 boff1 = swz((u32)(bd * 128 + (bq + 4) * 16));

    const int wm = wid & 3, wn = wid >> 2;
    float acc[2][4][4];
    #pragma unroll
    for (int a = 0; a < 2; a++)
        #pragma unroll
        for (int b = 0; b < 4; b++)
            #pragma unroll
            for (int c = 0; c < 4; c++) acc[a][b][c] = 0.0f;

    const u32 arow = (u32)((wm * 32 + (lane & 15)) * 128 + (lane >> 4) * 16);
    const u32 brow = (u32)((wn * 32 + (lane & 15)) * 128 + (lane >> 4) * 16);

    uint4 pa[2];
    pa[0] = *(const uint4*)(gA);  pa[1] = *(const uint4*)(gA + 16);
    CPA16(base_u + 16384 + boff0, gBrow + bq * 8);
    CPA16(base_u + 16384 + boff1, gBrow + (bq + 4) * 8);
    CPCOMMIT();
    conv_store_A(mlo, mhi, pa, dsm, aaddr);
    CPWAIT0();
    __syncthreads();

    for (int c = 0; c < NC1; c++) {
        const u32 bufo = (u32)(c & 1) * BUF_BYTES;
        const u32 nbufo = (u32)((c + 1) & 1) * BUF_BYTES;
        if (c + 1 < NC1) {
            int kb = (c + 1) * KT;
            pa[0] = *(const uint4*)(gA + kb);  pa[1] = *(const uint4*)(gA + kb + 16);
            CPA16(base_u + nbufo + 16384 + boff0, gBrow + kb + bq * 8);
            CPA16(base_u + nbufo + 16384 + boff1, gBrow + kb + (bq + 4) * 8);
            CPCOMMIT();
        }
        mma_chunk(base_u + bufo, base_u + bufo + 16384, arow, brow, acc);
        if (c + 1 < NC1) conv_store_A(mlo, mhi, pa, dsm + nbufo, aaddr);
        CPWAIT0();
        __syncthreads();
    }

    float* pdst = g_c1 + ((size_t)kc * NB + s) * NPOI * DD + (size_t)rowbase * DD;
    #pragma unroll
    for (int mi = 0; mi < 2; mi++) {
        #pragma unroll
        for (int e2 = 0; e2 < 2; e2++) {
            int pl = wm * 32 + mi * 16 + (lane >> 2) + e2 * 8;
            #pragma unroll
            for (int ni = 0; ni < 4; ni++) {
                int d = wn * 32 + ni * 8 + (lane & 3) * 2;
                *(float2*)(pdst + pl * DD + d) =
                    make_float2(acc[mi][ni][e2 * 2], acc[mi][ni][e2 * 2 + 1]);
            }
        }
    }
}

// layer-2: gathered 128 rows, K-split 8
__global__ __launch_bounds__(256, 2) void gemm2_mma_kernel() {
    const int t = threadIdx.x, wid = t >> 5, lane = t & 31;
    const int pb = blockIdx.x;
    const int s  = blockIdx.y;
    const int kc = blockIdx.z;
    u32* lutlo = (u32*)(dsm + LUT_OFF);
    u32* luthi = (u32*)(dsm + LUT_OFF + LUT_BYTES);
    int* srows = (int*)(dsm + LUT_OFF + 2 * LUT_BYTES);
    const u32 base_u = smem_u32(dsm);

    for (int e = t; e < NINT * 32; e += 256) {
        __half h = __float2half(g_cntf[s * NINT + (e >> 5)]);
        u32 bits = (u32)*(unsigned short*)&h;
        lutlo[e] = bits;
        luthi[e] = bits << 16;
    }
    if (t < 128) srows[t] = g_rows[s * NPOS + pb * 128 + t];
    __syncthreads();
    const u32* mlo = lutlo + lane;
    const u32* mhi = luthi + lane;

    const int pm = t >> 1, ph = t & 1;
    const int bd = t >> 2, bq = t & 3;
    const int kbase = kc * (NPOI / KC);
    const unsigned char* gA = g_bk + (size_t)srows[pm] * NPOI + kbase + ph * 32;
    const __half* gBrow = g_Y1t + ((size_t)s * DD + bd) * NPOI + kbase;
    u32 aaddr[4];
    #pragma unroll
    for (int u2 = 0; u2 < 2; u2++)
        #pragma unroll
        for (int hq = 0; hq < 2; hq++)
            aaddr[u2*2+hq] = swz((u32)(pm * 128 + ph * 64 + u2 * 32 + hq * 16));
    const u32 boff0 = swz((u32)(bd * 128 + bq * 16));
    const u32 boff1 = swz((u32)(bd * 128 + (bq + 4) * 16));

    const int wm = wid & 3, wn = wid >> 2;
    float acc[2][4][4];
    #pragma unroll
    for (int a = 0; a < 2; a++)
        #pragma unroll
        for (int b = 0; b < 4; b++)
            #pragma unroll
            for (int c = 0; c < 4; c++) acc[a][b][c] = 0.0f;

    const u32 arow = (u32)((wm * 32 + (lane & 15)) * 128 + (lane >> 4) * 16);
    const u32 brow = (u32)((wn * 32 + (lane & 15)) * 128 + (lane >> 4) * 16);

    uint4 pa[2];
    pa[0] = *(const uint4*)(gA);  pa[1] = *(const uint4*)(gA + 16);
    CPA16(base_u + 16384 + boff0, gBrow + bq * 8);
    CPA16(base_u + 16384 + boff1, gBrow + (bq + 4) * 8);
    CPCOMMIT();
    conv_store_A(mlo, mhi, pa, dsm, aaddr);
    CPWAIT0();
    __syncthreads();

    for (int c = 0; c < NC2; c++) {
        const u32 bufo = (u32)(c & 1) * BUF_BYTES;
        const u32 nbufo = (u32)((c + 1) & 1) * BUF_BYTES;
        if (c + 1 < NC2) {
            int kb = (c + 1) * KT;
            pa[0] = *(const uint4*)(gA + kb);  pa[1] = *(const uint4*)(gA + kb + 16);
            CPA16(base_u + nbufo + 16384 + boff0, gBrow + kb + bq * 8);
            CPA16(base_u + nbufo + 16384 + boff1, gBrow + kb + (bq + 4) * 8);
            CPCOMMIT();
        }
        mma_chunk(base_u + bufo, base_u + bufo + 16384, arow, brow, acc);
        if (c + 1 < NC2) conv_store_A(mlo, mhi, pa, dsm + nbufo, aaddr);
        CPWAIT0();
        __syncthreads();
    }

    float* pdst = g_part + ((size_t)kc * NB + s) * NPOS * DD + (size_t)pb * 128 * DD;
    #pragma unroll
    for (int mi = 0; mi < 2; mi++) {
        #pragma unroll
        for (int e2 = 0; e2 < 2; e2++) {
            int pl = wm * 32 + mi * 16 + (lane >> 2) + e2 * 8;
            #pragma unroll
            for (int ni = 0; ni < 4; ni++) {
                int d = wn * 32 + ni * 8 + (lane & 3) * 2;
                *(float2*)(pdst + pl * DD + d) =
                    make_float2(acc[mi][ni][e2 * 2], acc[mi][ni][e2 * 2 + 1]);
            }
        }
    }
}

__global__ __launch_bounds__(256) void finalize_kernel(const float* __restrict__ poi,
                                                       float* __restrict__ out) {
    int e = blockIdx.x * 256 + threadIdx.x;
    int d = e & 63, pl = e >> 6, pos = pl & 255, s = pl >> 8;
    int r = g_rows[s * NPOS + pos];
    float acc = 0.0f;
    #pragma unroll
    for (int kc = 0; kc < KC; kc++)
        acc += g_part[(((size_t)kc * NB + s) * NPOS + pos) * DD + d];
    acc *= (1.0f / 63.0f);
    float idg = g_invdeg[s * NPOI + r];
    float dterm = 1.0f - g_lut[s * NINT + g_diag[r]];
    size_t off = ((size_t)s * NPOI + r) * DD + d;
    float l2 = tanhf(idg * (acc + dterm * g_Y1[off]));
    float v = 8.0f * (poi[(size_t)(r + 1) * DD + d] + g_L1[off] + l2);
    int day = pos >> 6, l = pos & 63;
    out[(((size_t)(s * DAYS + day)) * LL + l) * DD + d] = v;
}

extern "C" void kernel_launch(void* const* d_in, const int* in_sizes, int n_in,
                              void* d_out, int out_size) {
    (void)in_sizes; (void)n_in; (void)out_size;
    const float* poi  = (const float*)d_in[0];
    const float* dist = (const float*)d_in[1];
    const int*   seq  = (const int*)d_in[2];
    const int*   ids  = (const int*)d_in[3];
    float* out = (float*)d_out;

    cudaFuncSetAttribute(gemm1_mma_kernel, cudaFuncAttributeMaxDynamicSharedMemorySize, SMEM_G);
    cudaFuncSetAttribute(gemm2_mma_kernel, cudaFuncAttributeMaxDynamicSharedMemorySize, SMEM_G2);

    setup_kernel    <<<1, 256>>>(dist, seq, ids);               // launch 0
    buckhist_kernel <<<NPOI, 256>>>(dist);                      // launch 1 (hist+deg fused)
    y0t_kernel      <<<dim3(NPOI / 64, NB), 256>>>(poi);        // launch 2
    gemm1_mma_kernel<<<dim3(NPOI / MT, NB, KS), 256, SMEM_G>>>(); // launch 3 (ncu slot)
    l1fin_kernel    <<<dim3(NPOI / 64, NB), 256>>>();
    gemm2_mma_kernel<<<dim3(2, NB, KC), 256, SMEM_G2>>>();
    finalize_kernel <<<(NB * NPOS * DD) / 256, 256>>>(poi, out);
}

// round 14
// speedup vs baseline: 1.0754x; 1.0361x over previous
#include <cuda_runtime.h>
#include <cuda_fp16.h>
#include <cstdint>
#include <cstddef>

#define NPOI 4096
#define DD   64
#define NB   8
#define DAYS 4
#define LL   64
#define NDROWS 32
#define NPOS   256
#define NINT 101
#define KC   8
#define KS   4
#define MT   128
#define KT   64
#define NC1  (NPOI/KS/KT)
#define NC2  (NPOI/KC/KT)
#define BUF_BYTES 24576
#define LUT_OFF   (2*BUF_BYTES)
#define LUT_BYTES (NINT*32*4)
#define SMEM_G    (LUT_OFF + 2*LUT_BYTES)
#define SMEM_G2   (SMEM_G + 512)

typedef unsigned long long u64;
typedef unsigned int u32;

__device__ __align__(16) unsigned char g_bk[(size_t)NPOI * NPOI];
__device__ unsigned char g_diag[NPOI];
__device__ float g_lut[NB * NINT];
__device__ float g_cntf[NB * NINT];
__device__ float g_invdeg[NB * NPOI];
__device__ int   g_rows[NB * NPOS];
__device__ float g_Y0[(size_t)NB * NPOI * DD];
__device__ float g_L1[(size_t)NB * NPOI * DD];
__device__ float g_Y1[(size_t)NB * NPOI * DD];
__device__ __align__(16) __half g_Yt[(size_t)NB * DD * NPOI];
__device__ __align__(16) __half g_Y1t[(size_t)NB * DD * NPOI];
__device__ float g_part[(size_t)KC * NB * NPOS * DD];
__device__ float g_c1[(size_t)KS * NB * NPOI * DD];

__device__ __forceinline__ u32 smem_u32(const void* p) {
    u32 a; asm("{ .reg .u64 t; cvta.to.shared.u64 t, %1; cvt.u32.u64 %0, t; }" : "=r"(a) : "l"(p));
    return a;
}
__device__ __forceinline__ u32 swz(u32 o) { return o ^ ((o >> 3) & 0x70); }
__device__ __forceinline__ void ldsm4(u32& r0, u32& r1, u32& r2, u32& r3, u32 a) {
    asm volatile("ldmatrix.sync.aligned.m8n8.x4.shared.b16 {%0,%1,%2,%3}, [%4];"
        : "=r"(r0), "=r"(r1), "=r"(r2), "=r"(r3) : "r"(a));
}
__device__ __forceinline__ void mma16816(float* c, const u32* a, u32 b0, u32 b1) {
    asm volatile("mma.sync.aligned.m16n8k16.row.col.f32.f16.f16.f32 "
        "{%0,%1,%2,%3}, {%4,%5,%6,%7}, {%8,%9}, {%0,%1,%2,%3};"
        : "+f"(c[0]), "+f"(c[1]), "+f"(c[2]), "+f"(c[3])
        : "r"(a[0]), "r"(a[1]), "r"(a[2]), "r"(a[3]), "r"(b0), "r"(b1));
}
#define CPA16(dst, src) asm volatile("cp.async.cg.shared.global [%0], [%1], 16;" :: "r"(dst), "l"(src))
#define CPCOMMIT()      asm volatile("cp.async.commit_group;")
#define CPWAIT0()       asm volatile("cp.async.wait_group 0;")

__device__ __forceinline__ void conv_store_A(const u32* lo, const u32* hi,
                                             const uint4* pa, char* Ab, const u32* aaddr) {
    #pragma unroll
    for (int u2 = 0; u2 < 2; u2++) {
        union { uint4 v; unsigned char b[16]; } q; q.v = pa[u2];
        #pragma unroll
        for (int hq = 0; hq < 2; hq++) {
            uint4 o;
            o.x = lo[q.b[hq*8+0]*32] | hi[q.b[hq*8+1]*32];
            o.y = lo[q.b[hq*8+2]*32] | hi[q.b[hq*8+3]*32];
            o.z = lo[q.b[hq*8+4]*32] | hi[q.b[hq*8+5]*32];
            o.w = lo[q.b[hq*8+6]*32] | hi[q.b[hq*8+7]*32];
            *(uint4*)(Ab + aaddr[u2*2+hq]) = o;
        }
    }
}

__device__ __forceinline__ void mma_chunk(u32 Ab_u, u32 Bb_u, u32 arow, u32 brow,
                                          float (&acc)[2][4][4]) {
    #pragma unroll
    for (int kk = 0; kk < 4; kk++) {
        const u32 kby = (u32)(kk * 32);
        u32 afr[2][4];
        #pragma unroll
        for (int mi = 0; mi < 2; mi++)
            ldsm4(afr[mi][0], afr[mi][1], afr[mi][2], afr[mi][3],
                  Ab_u + swz(arow + mi * 16 * 128 + kby));
        #pragma unroll
        for (int ni2 = 0; ni2 < 2; ni2++) {
            u32 r0, r1, r2, r3;
            ldsm4(r0, r1, r2, r3, Bb_u + swz(brow + ni2 * 16 * 128 + kby));
            #pragma unroll
            for (int mi = 0; mi < 2; mi++) {
                mma16816(acc[mi][ni2 * 2],     afr[mi], r0, r2);
                mma16816(acc[mi][ni2 * 2 + 1], afr[mi], r1, r3);
            }
        }
    }
}

__global__ __launch_bounds__(256) void setup_kernel(const float* __restrict__ dist,
                                                    const int* __restrict__ seq,
                                                    const int* __restrict__ ids) {
    __shared__ int sord[NDROWS];
    __shared__ int scnt[NB][NINT];
    int t = threadIdx.x;
    if (t < NDROWS) {
        int my = ids[t], pos = 0;
        for (int q = 0; q < NDROWS; q++) {
            int v = ids[q];
            if (v < my || (v == my && q < t)) pos++;
        }
        sord[pos] = t;
    }
    for (int e = t; e < NB * NINT; e += 256) (&scnt[0][0])[e] = 0;
    __syncthreads();
    for (int e = t; e < NB * NPOS; e += 256) {
        int s = e >> 8, pos = e & 255, day = pos >> 6, l = pos & 63;
        g_rows[e] = seq[sord[s * DAYS + day] * LL + l] - 1;
    }
    for (int e = t; e < NB * (LL - 1); e += 256) {
        int s = e / (LL - 1), tt = e % (LL - 1);
        int lrow = sord[s * DAYS + (DAYS - 1)];
        int a = seq[lrow * LL + tt] - 1;
        int b = seq[lrow * LL + tt + 1] - 1;
        float dv = dist[(size_t)a * NPOI + b];
        int idx = (int)ceilf(dv * 2.0f);
        idx = idx < 0 ? 0 : (idx > 100 ? 100 : idx);
        atomicAdd(&scnt[s][idx], 1);
    }
    __syncthreads();
    for (int e = t; e < NB * NINT; e += 256) {
        int cv = (&scnt[0][0])[e];
        g_lut[e]  = (float)cv / 63.0f;
        g_cntf[e] = (float)cv;
    }
}

__global__ __launch_bounds__(256) void buckhist_kernel(const float* __restrict__ dist) {
    __shared__ int sh[8][NINT + 3];
    __shared__ int hist[NINT];
    __shared__ float slut[NB * NINT];
    __shared__ int sdiag;
    int i = blockIdx.x, t = threadIdx.x, wid = t >> 5, lane = t & 31;
    for (int e = t; e < 8 * (NINT + 3); e += 256) (&sh[0][0])[e] = 0;
    for (int e = t; e < NB * NINT; e += 256) slut[e] = g_lut[e];
    __syncthreads();
    const float* row = dist + (size_t)i * NPOI;
    union { uint4 v; unsigned char b[16]; } o;
    #pragma unroll
    for (int v = 0; v < 4; v++) {
        float4 f = *(const float4*)(row + t * 16 + v * 4);
        o.b[v*4+0] = (unsigned char)min(100, (int)floorf(f.x * 2.0f) + 1);
        o.b[v*4+1] = (unsigned char)min(100, (int)floorf(f.y * 2.0f) + 1);
        o.b[v*4+2] = (unsigned char)min(100, (int)floorf(f.z * 2.0f) + 1);
        o.b[v*4+3] = (unsigned char)min(100, (int)floorf(f.w * 2.0f) + 1);
    }
    #pragma unroll
    for (int m = 0; m < 16; m++) atomicAdd(&sh[wid][o.b[m]], 1);
    *(uint4*)(g_bk + (size_t)i * NPOI + t * 16) = o.v;
    if ((i >> 4) == t) { g_diag[i] = o.b[i & 15]; sdiag = o.b[i & 15]; }
    __syncthreads();
    if (t < NINT) {
        int h = 0;
        #pragma unroll
        for (int w = 0; w < 8; w++) h += sh[w][t];
        hist[t] = h;
    }
    __syncthreads();
    {
        float part = 0.0f;
        for (int k = lane; k < NINT; k += 32)
            part += slut[wid * NINT + k] * (float)hist[k];
        #pragma unroll
        for (int off = 16; off > 0; off >>= 1)
            part += __shfl_down_sync(0xffffffffu, part, off);
        if (lane == 0) {
            float sum = part + 1.0f - slut[wid * NINT + sdiag];
            g_invdeg[wid * NPOI + i] = 1.0f / sqrtf(fmaxf(sum, 1e-24f));
        }
    }
}

__global__ __launch_bounds__(256) void y0t_kernel(const float* __restrict__ poi) {
    __shared__ float ts[64][65];
    int s = blockIdx.y, jbase = blockIdx.x * 64, t = threadIdx.x;
    #pragma unroll
    for (int r = 0; r < 16; r++) {
        int idx = r * 256 + t;
        int jl = idx >> 6, d = idx & 63;
        int j = jbase + jl;
        float y = poi[(size_t)(j + 1) * DD + d] * g_invdeg[s * NPOI + j];
        g_Y0[((size_t)s * NPOI + j) * DD + d] = y;
        ts[jl][d] = y;
    }
    __syncthreads();
    #pragma unroll
    for (int r = 0; r < 16; r++) {
        int idx = r * 256 + t;
        int d = idx >> 6, jl = idx & 63;
        g_Yt[((size_t)s * DD + d) * NPOI + jbase + jl] = __float2half(ts[jl][d]);
    }
}

__global__ __launch_bounds__(256) void l1fin_kernel() {
    __shared__ float ts[64][65];
    int s = blockIdx.y, jbase = blockIdx.x * 64, t = threadIdx.x;
    #pragma unroll
    for (int r = 0; r < 16; r++) {
        int idx = r * 256 + t;
        int jl = idx >> 6, d = idx & 63;
        int j = jbase + jl;
        size_t off = ((size_t)s * NPOI + j) * DD + d;
        float cf = 0.0f;
        #pragma unroll
        for (int kc = 0; kc < KS; kc++)
            cf += g_c1[(size_t)kc * NB * NPOI * DD + off];
        cf *= (1.0f / 63.0f);
        float idg = g_invdeg[s * NPOI + j];
        float dterm = 1.0f - g_lut[s * NINT + g_diag[j]];
        float l1 = tanhf(idg * (cf + dterm * g_Y0[off]));
        g_L1[off] = l1;
        float y1 = l1 * idg;
        g_Y1[off] = y1;
        ts[jl][d] = y1;
    }
    __syncthreads();
    #pragma unroll
    for (int r = 0; r < 16; r++) {
        int idx = r * 256 + t;
        int d = idx >> 6, jl = idx & 63;
        g_Y1t[((size_t)s * DD + d) * NPOI + jbase + jl] = __float2half(ts[jl][d]);
    }
}

extern __shared__ __align__(1024) char dsm[];

// layer-1: MT=128, K-split 4 -> 1024 CTAs, occ 3, two-table LUT
__global__ __launch_bounds__(256, 3) void gemm1_mma_kernel() {
    const int t = threadIdx.x, wid = t >> 5, lane = t & 31;
    const int s = blockIdx.y;
    const int kc = blockIdx.z;
    const int rowbase = blockIdx.x * MT;
    const int kbase = kc * (NPOI / KS);
    u32* lutlo = (u32*)(dsm + LUT_OFF);
    u32* luthi = (u32*)(dsm + LUT_OFF + LUT_BYTES);
    const u32 base_u = smem_u32(dsm);

    for (int e = t; e < NINT * 32; e += 256) {
        __half h = __float2half(g_cntf[s * NINT + (e >> 5)]);
        u32 bits = (u32)*(unsigned short*)&h;
        lutlo[e] = bits;
        luthi[e] = bits << 16;
    }
    __syncthreads();
    const u32* mlo = lutlo + lane;
    const u32* mhi = luthi + lane;

    const int pm = t >> 1, ph = t & 1;
    const int bd = t >> 2, bq = t & 3;
    const unsigned char* gA = g_bk + (size_t)(rowbase + pm) * NPOI + kbase + ph * 32;
    const __half* gBrow = g_Yt + ((size_t)s * DD + bd) * NPOI + kbase;
    u32 aaddr[4];
    #pragma unroll
    for (int u2 = 0; u2 < 2; u2++)
        #pragma unroll
        for (int hq = 0; hq < 2; hq++)
            aaddr[u2*2+hq] = swz((u32)(pm * 128 + ph * 64 + u2 * 32 + hq * 16));
    const u32 boff0 = swz((u32)(bd * 128 + bq * 16));
    const u32 boff1 = swz((u32)(bd * 128 + (bq + 4) * 16));

    const int wm = wid & 3, wn = wid >> 2;
    float acc[2][4][4];
    #pragma unroll
    for (int a = 0; a < 2; a++)
        #pragma unroll
        for (int b = 0; b < 4; b++)
            #pragma unroll
            for (int c = 0; c < 4; c++) acc[a][b][c] = 0.0f;

    const u32 arow = (u32)((wm * 32 + (lane & 15)) * 128 + (lane >> 4) * 16);
    const u32 brow = (u32)((wn * 32 + (lane & 15)) * 128 + (lane >> 4) * 16);

    uint4 pa[2];
    pa[0] = *(const uint4*)(gA);  pa[1] = *(const uint4*)(gA + 16);
    CPA16(base_u + 16384 + boff0, gBrow + bq * 8);
    CPA16(base_u + 16384 + boff1, gBrow + (bq + 4) * 8);
    CPCOMMIT();
    conv_store_A(mlo, mhi, pa, dsm, aaddr);
    CPWAIT0();
    __syncthreads();

    for (int c = 0; c < NC1; c++) {
        const u32 bufo = (u32)(c & 1) * BUF_BYTES;
        const u32 nbufo = (u32)((c + 1) & 1) * BUF_BYTES;
        if (c + 1 < NC1) {
            int kb = (c + 1) * KT;
            pa[0] = *(const uint4*)(gA + kb);  pa[1] = *(const uint4*)(gA + kb + 16);
            CPA16(base_u + nbufo + 16384 + boff0, gBrow + kb + bq * 8);
            CPA16(base_u + nbufo + 16384 + boff1, gBrow + kb + (bq + 4) * 8);
            CPCOMMIT();
        }
        mma_chunk(base_u + bufo, base_u + bufo + 16384, arow, brow, acc);
        if (c + 1 < NC1) conv_store_A(mlo, mhi, pa, dsm + nbufo, aaddr);
        CPWAIT0();
        __syncthreads();
    }

    float* pdst = g_c1 + ((size_t)kc * NB + s) * NPOI * DD + (size_t)rowbase * DD;
    #pragma unroll
    for (int mi = 0; mi < 2; mi++) {
        #pragma unroll
        for (int e2 = 0; e2 < 2; e2++) {
            int pl = wm * 32 + mi * 16 + (lane >> 2) + e2 * 8;
            #pragma unroll
            for (int ni = 0; ni < 4; ni++) {
                int d = wn * 32 + ni * 8 + (lane & 3) * 2;
                *(float2*)(pdst + pl * DD + d) =
                    make_float2(acc[mi][ni][e2 * 2], acc[mi][ni][e2 * 2 + 1]);
            }
        }
    }
}

__global__ __launch_bounds__(256, 2) void gemm2_mma_kernel() {
    const int t = threadIdx.x, wid = t >> 5, lane = t & 31;
    const int pb = blockIdx.x;
    const int s  = blockIdx.y;
    const int kc = blockIdx.z;
    u32* lutlo = (u32*)(dsm + LUT_OFF);
    u32* luthi = (u32*)(dsm + LUT_OFF + LUT_BYTES);
    int* srows = (int*)(dsm + LUT_OFF + 2 * LUT_BYTES);
    const u32 base_u = smem_u32(dsm);

    for (int e = t; e < NINT * 32; e += 256) {
        __half h = __float2half(g_cntf[s * NINT + (e >> 5)]);
        u32 bits = (u32)*(unsigned short*)&h;
        lutlo[e] = bits;
        luthi[e] = bits << 16;
    }
    if (t < 128) srows[t] = g_rows[s * NPOS + pb * 128 + t];
    __syncthreads();
    const u32* mlo = lutlo + lane;
    const u32* mhi = luthi + lane;

    const int pm = t >> 1, ph = t & 1;
    const int bd = t >> 2, bq = t & 3;
    const int kbase = kc * (NPOI / KC);
    const unsigned char* gA = g_bk + (size_t)srows[pm] * NPOI + kbase + ph * 32;
    const __half* gBrow = g_Y1t + ((size_t)s * DD + bd) * NPOI + kbase;
    u32 aaddr[4];
    #pragma unroll
    for (int u2 = 0; u2 < 2; u2++)
        #pragma unroll
        for (int hq = 0; hq < 2; hq++)
            aaddr[u2*2+hq] = swz((u32)(pm * 128 + ph * 64 + u2 * 32 + hq * 16));
    const u32 boff0 = swz((u32)(bd * 128 + bq * 16));
    const u32 boff1 = swz((u32)(bd * 128 + (bq + 4) * 16));

    const int wm = wid & 3, wn = wid >> 2;
    float acc[2][4][4];
    #pragma unroll
    for (int a = 0; a < 2; a++)
        #pragma unroll
        for (int b = 0; b < 4; b++)
            #pragma unroll
            for (int c = 0; c < 4; c++) acc[a][b][c] = 0.0f;

    const u32 arow = (u32)((wm * 32 + (lane & 15)) * 128 + (lane >> 4) * 16);
    const u32 brow = (u32)((wn * 32 + (lane & 15)) * 128 + (lane >> 4) * 16);

    uint4 pa[2];
    pa[0] = *(const uint4*)(gA);  pa[1] = *(const uint4*)(gA + 16);
    CPA16(base_u + 16384 + boff0, gBrow + bq * 8);
    CPA16(base_u + 16384 + boff1, gBrow + (bq + 4) * 8);
    CPCOMMIT();
    conv_store_A(mlo, mhi, pa, dsm, aaddr);
    CPWAIT0();
    __syncthreads();

    for (int c = 0; c < NC2; c++) {
        const u32 bufo = (u32)(c & 1) * BUF_BYTES;
        const u32 nbufo = (u32)((c + 1) & 1) * BUF_BYTES;
        if (c + 1 < NC2) {
            int kb = (c + 1) * KT;
            pa[0] = *(const uint4*)(gA + kb);  pa[1] = *(const uint4*)(gA + kb + 16);
            CPA16(base_u + nbufo + 16384 + boff0, gBrow + kb + bq * 8);
            CPA16(base_u + nbufo + 16384 + boff1, gBrow + kb + (bq + 4) * 8);
            CPCOMMIT();
        }
        mma_chunk(base_u + bufo, base_u + bufo + 16384, arow, brow, acc);
        if (c + 1 < NC2) conv_store_A(mlo, mhi, pa, dsm + nbufo, aaddr);
        CPWAIT0();
        __syncthreads();
    }

    float* pdst = g_part + ((size_t)kc * NB + s) * NPOS * DD + (size_t)pb * 128 * DD;
    #pragma unroll
    for (int mi = 0; mi < 2; mi++) {
        #pragma unroll
        for (int e2 = 0; e2 < 2; e2++) {
            int pl = wm * 32 + mi * 16 + (lane >> 2) + e2 * 8;
            #pragma unroll
            for (int ni = 0; ni < 4; ni++) {
                int d = wn * 32 + ni * 8 + (lane & 3) * 2;
                *(float2*)(pdst + pl * DD + d) =
                    make_float2(acc[mi][ni][e2 * 2], acc[mi][ni][e2 * 2 + 1]);
            }
        }
    }
}

__global__ __launch_bounds__(256) void finalize_kernel(const float* __restrict__ poi,
                                                       float* __restrict__ out) {
    int e = blockIdx.x * 256 + threadIdx.x;
    int d = e & 63, pl = e >> 6, pos = pl & 255, s = pl >> 8;
    int r = g_rows[s * NPOS + pos];
    float acc = 0.0f;
    #pragma unroll
    for (int kc = 0; kc < KC; kc++)
        acc += g_part[(((size_t)kc * NB + s) * NPOS + pos) * DD + d];
    acc *= (1.0f / 63.0f);
    float idg = g_invdeg[s * NPOI + r];
    float dterm = 1.0f - g_lut[s * NINT + g_diag[r]];
    size_t off = ((size_t)s * NPOI + r) * DD + d;
    float l2 = tanhf(idg * (acc + dterm * g_Y1[off]));
    float v = 8.0f * (poi[(size_t)(r + 1) * DD + d] + g_L1[off] + l2);
    int day = pos >> 6, l = pos & 63;
    out[(((size_t)(s * DAYS + day)) * LL + l) * DD + d] = v;
}

extern "C" void kernel_launch(void* const* d_in, const int* in_sizes, int n_in,
                              void* d_out, int out_size) {
    (void)in_sizes; (void)n_in; (void)out_size;
    const float* poi  = (const float*)d_in[0];
    const float* dist = (const float*)d_in[1];
    const int*   seq  = (const int*)d_in[2];
    const int*   ids  = (const int*)d_in[3];
    float* out = (float*)d_out;

    cudaFuncSetAttribute(gemm1_mma_kernel, cudaFuncAttributeMaxDynamicSharedMemorySize, SMEM_G);
    cudaFuncSetAttribute(gemm2_mma_kernel, cudaFuncAttributeMaxDynamicSharedMemorySize, SMEM_G2);

    setup_kernel    <<<1, 256>>>(dist, seq, ids);
    buckhist_kernel <<<NPOI, 256>>>(dist);
    y0t_kernel      <<<dim3(NPOI / 64, NB), 256>>>(poi);
    gemm1_mma_kernel<<<dim3(NPOI / MT, NB, KS), 256, SMEM_G>>>(); // launch 3 (ncu slot)
    l1fin_kernel    <<<dim3(NPOI / 64, NB), 256>>>();
    gemm2_mma_kernel<<<dim3(2, NB, KC), 256, SMEM_G2>>>();
    finalize_kernel <<<(NB * NPOS * DD) / 256, 256>>>(poi, out);
}

// round 15
// speedup vs baseline: 1.1287x; 1.0496x over previous
#include <cuda_runtime.h>
#include <cuda_fp16.h>
#include <cstdint>
#include <cstddef>

#define NPOI 4096
#define DD   64
#define NB   8
#define DAYS 4
#define LL   64
#define NDROWS 32
#define NPOS   256
#define NINT 101
#define KC   8
#define KS   4
#define MT   128
#define KT   64
#define NC1  (NPOI/KS/KT)
#define NC2  (NPOI/KC/KT)
#define BUF_BYTES 24576
#define LUT_OFF   (2*BUF_BYTES)
#define LUT_BYTES (NINT*32*4)
#define SMEM_G    (LUT_OFF + 2*LUT_BYTES)
#define SMEM_G2   (SMEM_G + 512)

typedef unsigned long long u64;
typedef unsigned int u32;

__device__ __align__(16) unsigned char g_bk[(size_t)NPOI * NPOI];
__device__ unsigned char g_diag[NPOI];
__device__ float g_lut[NB * NINT];
__device__ float g_cntf[NB * NINT];
__device__ float g_invdeg[NB * NPOI];
__device__ int   g_rows[NB * NPOS];
__device__ __align__(16) __half g_Yt[(size_t)NB * DD * NPOI];
__device__ __align__(16) __half g_Y1t[(size_t)NB * DD * NPOI];
__device__ float g_part[(size_t)KC * NB * NPOS * DD];
__device__ float g_c1[(size_t)KS * NB * NPOI * DD];

__device__ __forceinline__ u32 smem_u32(const void* p) {
    u32 a; asm("{ .reg .u64 t; cvta.to.shared.u64 t, %1; cvt.u32.u64 %0, t; }" : "=r"(a) : "l"(p));
    return a;
}
__device__ __forceinline__ u32 swz(u32 o) { return o ^ ((o >> 3) & 0x70); }
__device__ __forceinline__ void ldsm4(u32& r0, u32& r1, u32& r2, u32& r3, u32 a) {
    asm volatile("ldmatrix.sync.aligned.m8n8.x4.shared.b16 {%0,%1,%2,%3}, [%4];"
        : "=r"(r0), "=r"(r1), "=r"(r2), "=r"(r3) : "r"(a));
}
__device__ __forceinline__ void mma16816(float* c, const u32* a, u32 b0, u32 b1) {
    asm volatile("mma.sync.aligned.m16n8k16.row.col.f32.f16.f16.f32 "
        "{%0,%1,%2,%3}, {%4,%5,%6,%7}, {%8,%9}, {%0,%1,%2,%3};"
        : "+f"(c[0]), "+f"(c[1]), "+f"(c[2]), "+f"(c[3])
        : "r"(a[0]), "r"(a[1]), "r"(a[2]), "r"(a[3]), "r"(b0), "r"(b1));
}
#define CPA16(dst, src) asm volatile("cp.async.cg.shared.global [%0], [%1], 16;" :: "r"(dst), "l"(src))
#define CPCOMMIT()      asm volatile("cp.async.commit_group;")
#define CPWAIT0()       asm volatile("cp.async.wait_group 0;")

__device__ __forceinline__ void conv_store_A(const u32* lo, const u32* hi,
                                             const uint4* pa, char* Ab, const u32* aaddr) {
    #pragma unroll
    for (int u2 = 0; u2 < 2; u2++) {
        union { uint4 v; unsigned char b[16]; } q; q.v = pa[u2];
        #pragma unroll
        for (int hq = 0; hq < 2; hq++) {
            uint4 o;
            o.x = lo[q.b[hq*8+0]*32] | hi[q.b[hq*8+1]*32];
            o.y = lo[q.b[hq*8+2]*32] | hi[q.b[hq*8+3]*32];
            o.z = lo[q.b[hq*8+4]*32] | hi[q.b[hq*8+5]*32];
            o.w = lo[q.b[hq*8+6]*32] | hi[q.b[hq*8+7]*32];
            *(uint4*)(Ab + aaddr[u2*2+hq]) = o;
        }
    }
}

__device__ __forceinline__ void mma_chunk(u32 Ab_u, u32 Bb_u, u32 arow, u32 brow,
                                          float (&acc)[2][4][4]) {
    #pragma unroll
    for (int kk = 0; kk < 4; kk++) {
        const u32 kby = (u32)(kk * 32);
        u32 afr[2][4];
        #pragma unroll
        for (int mi = 0; mi < 2; mi++)
            ldsm4(afr[mi][0], afr[mi][1], afr[mi][2], afr[mi][3],
                  Ab_u + swz(arow + mi * 16 * 128 + kby));
        #pragma unroll
        for (int ni2 = 0; ni2 < 2; ni2++) {
            u32 r0, r1, r2, r3;
            ldsm4(r0, r1, r2, r3, Bb_u + swz(brow + ni2 * 16 * 128 + kby));
            #pragma unroll
            for (int mi = 0; mi < 2; mi++) {
                mma16816(acc[mi][ni2 * 2],     afr[mi], r0, r2);
                mma16816(acc[mi][ni2 * 2 + 1], afr[mi], r1, r3);
            }
        }
    }
}

__global__ __launch_bounds__(256) void setup_kernel(const float* __restrict__ dist,
                                                    const int* __restrict__ seq,
                                                    const int* __restrict__ ids) {
    __shared__ int sord[NDROWS];
    __shared__ int scnt[NB][NINT];
    int t = threadIdx.x;
    if (t < NDROWS) {
        int my = ids[t], pos = 0;
        for (int q = 0; q < NDROWS; q++) {
            int v = ids[q];
            if (v < my || (v == my && q < t)) pos++;
        }
        sord[pos] = t;
    }
    for (int e = t; e < NB * NINT; e += 256) (&scnt[0][0])[e] = 0;
    __syncthreads();
    for (int e = t; e < NB * NPOS; e += 256) {
        int s = e >> 8, pos = e & 255, day = pos >> 6, l = pos & 63;
        g_rows[e] = seq[sord[s * DAYS + day] * LL + l] - 1;
    }
    for (int e = t; e < NB * (LL - 1); e += 256) {
        int s = e / (LL - 1), tt = e % (LL - 1);
        int lrow = sord[s * DAYS + (DAYS - 1)];
        int a = seq[lrow * LL + tt] - 1;
        int b = seq[lrow * LL + tt + 1] - 1;
        float dv = dist[(size_t)a * NPOI + b];
        int idx = (int)ceilf(dv * 2.0f);
        idx = idx < 0 ? 0 : (idx > 100 ? 100 : idx);
        atomicAdd(&scnt[s][idx], 1);
    }
    __syncthreads();
    for (int e = t; e < NB * NINT; e += 256) {
        int cv = (&scnt[0][0])[e];
        g_lut[e]  = (float)cv / 63.0f;
        g_cntf[e] = (float)cv;
    }
}

__global__ __launch_bounds__(256) void buckhist_kernel(const float* __restrict__ dist) {
    __shared__ int sh[8][NINT + 3];
    __shared__ int hist[NINT];
    __shared__ float slut[NB * NINT];
    __shared__ int sdiag;
    int i = blockIdx.x, t = threadIdx.x, wid = t >> 5, lane = t & 31;
    for (int e = t; e < 8 * (NINT + 3); e += 256) (&sh[0][0])[e] = 0;
    for (int e = t; e < NB * NINT; e += 256) slut[e] = g_lut[e];
    __syncthreads();
    const float* row = dist + (size_t)i * NPOI;
    union { uint4 v; unsigned char b[16]; } o;
    #pragma unroll
    for (int v = 0; v < 4; v++) {
        float4 f = *(const float4*)(row + t * 16 + v * 4);
        o.b[v*4+0] = (unsigned char)min(100, (int)floorf(f.x * 2.0f) + 1);
        o.b[v*4+1] = (unsigned char)min(100, (int)floorf(f.y * 2.0f) + 1);
        o.b[v*4+2] = (unsigned char)min(100, (int)floorf(f.z * 2.0f) + 1);
        o.b[v*4+3] = (unsigned char)min(100, (int)floorf(f.w * 2.0f) + 1);
    }
    #pragma unroll
    for (int m = 0; m < 16; m++) atomicAdd(&sh[wid][o.b[m]], 1);
    *(uint4*)(g_bk + (size_t)i * NPOI + t * 16) = o.v;
    if ((i >> 4) == t) { g_diag[i] = o.b[i & 15]; sdiag = o.b[i & 15]; }
    __syncthreads();
    if (t < NINT) {
        int h = 0;
        #pragma unroll
        for (int w = 0; w < 8; w++) h += sh[w][t];
        hist[t] = h;
    }
    __syncthreads();
    {
        float part = 0.0f;
        for (int k = lane; k < NINT; k += 32)
            part += slut[wid * NINT + k] * (float)hist[k];
        #pragma unroll
        for (int off = 16; off > 0; off >>= 1)
            part += __shfl_down_sync(0xffffffffu, part, off);
        if (lane == 0) {
            float sum = part + 1.0f - slut[wid * NINT + sdiag];
            g_invdeg[wid * NPOI + i] = 1.0f / sqrtf(fmaxf(sum, 1e-24f));
        }
    }
}

// writes ONLY transposed fp16 Yt (Y0 recomputed where needed)
__global__ __launch_bounds__(256) void y0t_kernel(const float* __restrict__ poi) {
    __shared__ float ts[64][65];
    int s = blockIdx.y, jbase = blockIdx.x * 64, t = threadIdx.x;
    #pragma unroll
    for (int r = 0; r < 16; r++) {
        int idx = r * 256 + t;
        int jl = idx >> 6, d = idx & 63;
        int j = jbase + jl;
        ts[jl][d] = poi[(size_t)(j + 1) * DD + d] * g_invdeg[s * NPOI + j];
    }
    __syncthreads();
    #pragma unroll
    for (int r = 0; r < 16; r++) {
        int idx = r * 256 + t;
        int d = idx >> 6, jl = idx & 63;
        g_Yt[((size_t)s * DD + d) * NPOI + jbase + jl] = __float2half(ts[jl][d]);
    }
}

// sum K-split partials, /63, diag fix (recompute y0 from poi), tanh -> ONLY Y1t
__global__ __launch_bounds__(256) void l1fin_kernel(const float* __restrict__ poi) {
    __shared__ float ts[64][65];
    int s = blockIdx.y, jbase = blockIdx.x * 64, t = threadIdx.x;
    #pragma unroll
    for (int r = 0; r < 16; r++) {
        int idx = r * 256 + t;
        int jl = idx >> 6, d = idx & 63;
        int j = jbase + jl;
        size_t off = ((size_t)s * NPOI + j) * DD + d;
        float cf = 0.0f;
        #pragma unroll
        for (int kc = 0; kc < KS; kc++)
            cf += g_c1[(size_t)kc * NB * NPOI * DD + off];
        cf *= (1.0f / 63.0f);
        float idg = g_invdeg[s * NPOI + j];
        float dterm = 1.0f - g_lut[s * NINT + g_diag[j]];
        float y0 = poi[(size_t)(j + 1) * DD + d] * idg;
        float l1 = tanhf(idg * (cf + dterm * y0));
        ts[jl][d] = l1 * idg;
    }
    __syncthreads();
    #pragma unroll
    for (int r = 0; r < 16; r++) {
        int idx = r * 256 + t;
        int d = idx >> 6, jl = idx & 63;
        g_Y1t[((size_t)s * DD + d) * NPOI + jbase + jl] = __float2half(ts[jl][d]);
    }
}

extern __shared__ __align__(1024) char dsm[];

// layer-1: MT=128, K-split 4 -> 1024 CTAs, occ 3, two-table LUT
__global__ __launch_bounds__(256, 3) void gemm1_mma_kernel() {
    const int t = threadIdx.x, wid = t >> 5, lane = t & 31;
    const int s = blockIdx.y;
    const int kc = blockIdx.z;
    const int rowbase = blockIdx.x * MT;
    const int kbase = kc * (NPOI / KS);
    u32* lutlo = (u32*)(dsm + LUT_OFF);
    u32* luthi = (u32*)(dsm + LUT_OFF + LUT_BYTES);
    const u32 base_u = smem_u32(dsm);

    for (int e = t; e < NINT * 32; e += 256) {
        __half h = __float2half(g_cntf[s * NINT + (e >> 5)]);
        u32 bits = (u32)*(unsigned short*)&h;
        lutlo[e] = bits;
        luthi[e] = bits << 16;
    }
    __syncthreads();
    const u32* mlo = lutlo + lane;
    const u32* mhi = luthi + lane;

    const int pm = t >> 1, ph = t & 1;
    const int bd = t >> 2, bq = t & 3;
    const unsigned char* gA = g_bk + (size_t)(rowbase + pm) * NPOI + kbase + ph * 32;
    const __half* gBrow = g_Yt + ((size_t)s * DD + bd) * NPOI + kbase;
    u32 aaddr[4];
    #pragma unroll
    for (int u2 = 0; u2 < 2; u2++)
        #pragma unroll
        for (int hq = 0; hq < 2; hq++)
            aaddr[u2*2+hq] = swz((u32)(pm * 128 + ph * 64 + u2 * 32 + hq * 16));
    const u32 boff0 = swz((u32)(bd * 128 + bq * 16));
    const u32 boff1 = swz((u32)(bd * 128 + (bq + 4) * 16));

    const int wm = wid & 3, wn = wid >> 2;
    float acc[2][4][4];
    #pragma unroll
    for (int a = 0; a < 2; a++)
        #pragma unroll
        for (int b = 0; b < 4; b++)
            #pragma unroll
            for (int c = 0; c < 4; c++) acc[a][b][c] = 0.0f;

    const u32 arow = (u32)((wm * 32 + (lane & 15)) * 128 + (lane >> 4) * 16);
    const u32 brow = (u32)((wn * 32 + (lane & 15)) * 128 + (lane >> 4) * 16);

    uint4 pa[2];
    pa[0] = *(const uint4*)(gA);  pa[1] = *(const uint4*)(gA + 16);
    CPA16(base_u + 16384 + boff0, gBrow + bq * 8);
    CPA16(base_u + 16384 + boff1, gBrow + (bq + 4) * 8);
    CPCOMMIT();
    conv_store_A(mlo, mhi, pa, dsm, aaddr);
    CPWAIT0();
    __syncthreads();

    for (int c = 0; c < NC1; c++) {
        const u32 bufo = (u32)(c & 1) * BUF_BYTES;
        const u32 nbufo = (u32)((c + 1) & 1) * BUF_BYTES;
        if (c + 1 < NC1) {
            int kb = (c + 1) * KT;
            pa[0] = *(const uint4*)(gA + kb);  pa[1] = *(const uint4*)(gA + kb + 16);
            CPA16(base_u + nbufo + 16384 + boff0, gBrow + kb + bq * 8);
            CPA16(base_u + nbufo + 16384 + boff1, gBrow + kb + (bq + 4) * 8);
            CPCOMMIT();
        }
        mma_chunk(base_u + bufo, base_u + bufo + 16384, arow, brow, acc);
        if (c + 1 < NC1) conv_store_A(mlo, mhi, pa, dsm + nbufo, aaddr);
        CPWAIT0();
        __syncthreads();
    }

    float* pdst = g_c1 + ((size_t)kc * NB + s) * NPOI * DD + (size_t)rowbase * DD;
    #pragma unroll
    for (int mi = 0; mi < 2; mi++) {
        #pragma unroll
        for (int e2 = 0; e2 < 2; e2++) {
            int pl = wm * 32 + mi * 16 + (lane >> 2) + e2 * 8;
            #pragma unroll
            for (int ni = 0; ni < 4; ni++) {
                int d = wn * 32 + ni * 8 + (lane & 3) * 2;
                *(float2*)(pdst + pl * DD + d) =
                    make_float2(acc[mi][ni][e2 * 2], acc[mi][ni][e2 * 2 + 1]);
            }
        }
    }
}

__global__ __launch_bounds__(256, 2) void gemm2_mma_kernel() {
    const int t = threadIdx.x, wid = t >> 5, lane = t & 31;
    const int pb = blockIdx.x;
    const int s  = blockIdx.y;
    const int kc = blockIdx.z;
    u32* lutlo = (u32*)(dsm + LUT_OFF);
    u32* luthi = (u32*)(dsm + LUT_OFF + LUT_BYTES);
    int* srows = (int*)(dsm + LUT_OFF + 2 * LUT_BYTES);
    const u32 base_u = smem_u32(dsm);

    for (int e = t; e < NINT * 32; e += 256) {
        __half h = __float2half(g_cntf[s * NINT + (e >> 5)]);
        u32 bits = (u32)*(unsigned short*)&h;
        lutlo[e] = bits;
        luthi[e] = bits << 16;
    }
    if (t < 128) srows[t] = g_rows[s * NPOS + pb * 128 + t];
    __syncthreads();
    const u32* mlo = lutlo + lane;
    const u32* mhi = luthi + lane;

    const int pm = t >> 1, ph = t & 1;
    const int bd = t >> 2, bq = t & 3;
    const int kbase = kc * (NPOI / KC);
    const unsigned char* gA = g_bk + (size_t)srows[pm] * NPOI + kbase + ph * 32;
    const __half* gBrow = g_Y1t + ((size_t)s * DD + bd) * NPOI + kbase;
    u32 aaddr[4];
    #pragma unroll
    for (int u2 = 0; u2 < 2; u2++)
        #pragma unroll
        for (int hq = 0; hq < 2; hq++)
            aaddr[u2*2+hq] = swz((u32)(pm * 128 + ph * 64 + u2 * 32 + hq * 16));
    const u32 boff0 = swz((u32)(bd * 128 + bq * 16));
    const u32 boff1 = swz((u32)(bd * 128 + (bq + 4) * 16));

    const int wm = wid & 3, wn = wid >> 2;
    float acc[2][4][4];
    #pragma unroll
    for (int a = 0; a < 2; a++)
        #pragma unroll
        for (int b = 0; b < 4; b++)
            #pragma unroll
            for (int c = 0; c < 4; c++) acc[a][b][c] = 0.0f;

    const u32 arow = (u32)((wm * 32 + (lane & 15)) * 128 + (lane >> 4) * 16);
    const u32 brow = (u32)((wn * 32 + (lane & 15)) * 128 + (lane >> 4) * 16);

    uint4 pa[2];
    pa[0] = *(const uint4*)(gA);  pa[1] = *(const uint4*)(gA + 16);
    CPA16(base_u + 16384 + boff0, gBrow + bq * 8);
    CPA16(base_u + 16384 + boff1, gBrow + (bq + 4) * 8);
    CPCOMMIT();
    conv_store_A(mlo, mhi, pa, dsm, aaddr);
    CPWAIT0();
    __syncthreads();

    for (int c = 0; c < NC2; c++) {
        const u32 bufo = (u32)(c & 1) * BUF_BYTES;
        const u32 nbufo = (u32)((c + 1) & 1) * BUF_BYTES;
        if (c + 1 < NC2) {
            int kb = (c + 1) * KT;
            pa[0] = *(const uint4*)(gA + kb);  pa[1] = *(const uint4*)(gA + kb + 16);
            CPA16(base_u + nbufo + 16384 + boff0, gBrow + kb + bq * 8);
            CPA16(base_u + nbufo + 16384 + boff1, gBrow + kb + (bq + 4) * 8);
            CPCOMMIT();
        }
        mma_chunk(base_u + bufo, base_u + bufo + 16384, arow, brow, acc);
        if (c + 1 < NC2) conv_store_A(mlo, mhi, pa, dsm + nbufo, aaddr);
        CPWAIT0();
        __syncthreads();
    }

    float* pdst = g_part + ((size_t)kc * NB + s) * NPOS * DD + (size_t)pb * 128 * DD;
    #pragma unroll
    for (int mi = 0; mi < 2; mi++) {
        #pragma unroll
        for (int e2 = 0; e2 < 2; e2++) {
            int pl = wm * 32 + mi * 16 + (lane >> 2) + e2 * 8;
            #pragma unroll
            for (int ni = 0; ni < 4; ni++) {
                int d = wn * 32 + ni * 8 + (lane & 3) * 2;
                *(float2*)(pdst + pl * DD + d) =
                    make_float2(acc[mi][ni][e2 * 2], acc[mi][ni][e2 * 2 + 1]);
            }
        }
    }
}

__global__ __launch_bounds__(256) void finalize_kernel(const float* __restrict__ poi,
                                                       float* __restrict__ out) {
    int e = blockIdx.x * 256 + threadIdx.x;
    int d = e & 63, pl = e >> 6, pos = pl & 255, s = pl >> 8;
    int r = g_rows[s * NPOS + pos];
    float acc = 0.0f;
    #pragma unroll
    for (int kc = 0; kc < KC; kc++)
        acc += g_part[(((size_t)kc * NB + s) * NPOS + pos) * DD + d];
    acc *= (1.0f / 63.0f);
    float idg = g_invdeg[s * NPOI + r];
    float dterm = 1.0f - g_lut[s * NINT + g_diag[r]];
    float y1 = __half2float(g_Y1t[((size_t)s * DD + d) * NPOI + r]);
    float l1 = y1 / idg;
    float l2 = tanhf(idg * (acc + dterm * y1));
    float v = 8.0f * (poi[(size_t)(r + 1) * DD + d] + l1 + l2);
    int day = pos >> 6, l = pos & 63;
    out[(((size_t)(s * DAYS + day)) * LL + l) * DD + d] = v;
}

extern "C" void kernel_launch(void* const* d_in, const int* in_sizes, int n_in,
                              void* d_out, int out_size) {
    (void)in_sizes; (void)n_in; (void)out_size;
    const float* poi  = (const float*)d_in[0];
    const float* dist = (const float*)d_in[1];
    const int*   seq  = (const int*)d_in[2];
    const int*   ids  = (const int*)d_in[3];
    float* out = (float*)d_out;

    cudaFuncSetAttribute(gemm1_mma_kernel, cudaFuncAttributeMaxDynamicSharedMemorySize, SMEM_G);
    cudaFuncSetAttribute(gemm2_mma_kernel, cudaFuncAttributeMaxDynamicSharedMemorySize, SMEM_G2);

    setup_kernel    <<<1, 256>>>(dist, seq, ids);
    buckhist_kernel <<<NPOI, 256>>>(dist);
    y0t_kernel      <<<dim3(NPOI / 64, NB), 256>>>(poi);
    gemm1_mma_kernel<<<dim3(NPOI / MT, NB, KS), 256, SMEM_G>>>(); // launch 3 (ncu slot)
    l1fin_kernel    <<<dim3(NPOI / 64, NB), 256>>>(poi);
    gemm2_mma_kernel<<<dim3(2, NB, KC), 256, SMEM_G2>>>();
    finalize_kernel <<<(NB * NPOS * DD) / 256, 256>>>(poi, out);
}